// round 4
// baseline (speedup 1.0000x reference)
#include <cuda_runtime.h>
#include <cuda_bf16.h>
#include <math.h>
#include <cstdint>

#define NN 100000
#define EE 1600000
#define DD 128
#define NROWS4 ((NN * DD) / 4)

// ---------------- scratch (static device globals; no allocation) -------------
// packed activation format: uint32 = bf16 hi (low 16) | bf16 lo (high 16); value = hi + lo
__device__ __align__(16) uint32_t g_pk0[NN * DD];
__device__ __align__(16) uint32_t g_pk1[NN * DD];
__device__ __align__(16) uint32_t g_pa [NN * DD];

__device__ int   g_col[EE];
__device__ int   g_cnt[NN];
__device__ int   g_rowptr[NN + 1];
__device__ int   g_wcur[NN];
__device__ float g_invdeg[NN];
__device__ int   g_tmp[NN];
__device__ int   g_bsum[128];
__device__ int   g_is64;

// pre-split transposed weights per layer: [n=128][k=256] bf16 hi/lo
__device__ __align__(16) __nv_bfloat16 g_wt_hi[3][128 * 256];
__device__ __align__(16) __nv_bfloat16 g_wt_lo[3][128 * 256];

// ================= helpers =====================================================
__device__ __forceinline__ uint32_t smem_u32(const void* p) {
    uint32_t a;
    asm("{ .reg .u64 t; cvta.to.shared.u64 t, %1; cvt.u32.u64 %0, t; }" : "=r"(a) : "l"(p));
    return a;
}
__device__ __forceinline__ void ldm_x4(uint32_t* r, uint32_t addr) {
    asm volatile("ldmatrix.sync.aligned.m8n8.x4.shared.b16 {%0,%1,%2,%3}, [%4];"
                 : "=r"(r[0]), "=r"(r[1]), "=r"(r[2]), "=r"(r[3]) : "r"(addr));
}
__device__ __forceinline__ void mma16816(float* c, const uint32_t* a, uint32_t b0, uint32_t b1) {
    asm volatile(
        "mma.sync.aligned.m16n8k16.row.col.f32.bf16.bf16.f32 "
        "{%0,%1,%2,%3},{%4,%5,%6,%7},{%8,%9},{%0,%1,%2,%3};"
        : "+f"(c[0]), "+f"(c[1]), "+f"(c[2]), "+f"(c[3])
        : "r"(a[0]), "r"(a[1]), "r"(a[2]), "r"(a[3]), "r"(b0), "r"(b1));
}
__device__ __forceinline__ uint32_t packsplit(float a) {
    __nv_bfloat16 h = __float2bfloat16(a);
    float r = a - __bfloat162float(h);
    __nv_bfloat16 l = __float2bfloat16(r);
    return (uint32_t)__bfloat16_as_ushort(h) | ((uint32_t)__bfloat16_as_ushort(l) << 16);
}
__device__ __forceinline__ float unpackf(uint32_t p) {
    return __uint_as_float(p << 16) + __uint_as_float(p & 0xffff0000u);
}

// ---------------- CSR build (fused) --------------------------------------------
__global__ void k_probe_zero(const long long* __restrict__ p) {
    int i = blockIdx.x * blockDim.x + threadIdx.x;
    if (i < NN) g_cnt[i] = 0;
    if (blockIdx.x == 0) {
        long long v = p[threadIdx.x];
        int bad = (v < 0 || v >= NN) ? 1 : 0;
        unsigned m = __ballot_sync(0xffffffffu, bad);
        __shared__ int any;
        if (threadIdx.x == 0) any = 0;
        __syncthreads();
        if ((threadIdx.x & 31) == 0 && m) atomicOr(&any, 1);
        __syncthreads();
        if (threadIdx.x == 0) g_is64 = any ? 0 : 1;
    }
}
__global__ void k_hist(const void* __restrict__ ei) {
    int e = blockIdx.x * blockDim.x + threadIdx.x;
    if (e >= EE) return;
    int d = g_is64 ? (int)((const long long*)ei)[EE + e] : ((const int*)ei)[EE + e];
    atomicAdd(&g_cnt[d], 1);
}
__global__ void k_scan1() {
    __shared__ int s[1024];
    int tid = threadIdx.x;
    int gid = blockIdx.x * 1024 + tid;
    int v = (gid < NN) ? g_cnt[gid] : 0;
    s[tid] = v;
    __syncthreads();
    for (int off = 1; off < 1024; off <<= 1) {
        int t = (tid >= off) ? s[tid - off] : 0;
        __syncthreads();
        s[tid] += t;
        __syncthreads();
    }
    int incl = s[tid];
    if (gid < NN) g_tmp[gid] = incl - v;
    if (tid == 1023) g_bsum[blockIdx.x] = incl;
}
// scan3 with inline block-sum prefix (each 256-block covers one quarter of a 1024 scan1 block)
__global__ void k_scan3b() {
    __shared__ int base;
    int sbk = blockIdx.x >> 2;
    if (threadIdx.x < 32) {
        int a = 0;
        for (int i = threadIdx.x; i < sbk; i += 32) a += g_bsum[i];
#pragma unroll
        for (int o = 16; o > 0; o >>= 1) a += __shfl_xor_sync(0xffffffffu, a, o);
        if (threadIdx.x == 0) base = a;
    }
    __syncthreads();
    int i = blockIdx.x * 256 + threadIdx.x;
    if (i < NN) {
        int rp = g_tmp[i] + base;
        g_rowptr[i] = rp;
        g_wcur[i] = rp;
        int c = g_cnt[i];
        g_invdeg[i] = 1.0f / (float)(c > 1 ? c : 1);
        if (i == 0) g_rowptr[NN] = EE;
    }
}
__global__ void k_scatter(const void* __restrict__ ei) {
    int e = blockIdx.x * blockDim.x + threadIdx.x;
    if (e >= EE) return;
    int s, d;
    if (g_is64) {
        const long long* p = (const long long*)ei;
        s = (int)p[e]; d = (int)p[EE + e];
    } else {
        const int* p = (const int*)ei;
        s = p[e]; d = p[EE + e];
    }
    g_col[atomicAdd(&g_wcur[d], 1)] = s;
}

// ---------------- mean aggregation: one warp per node, packed out -------------
__global__ void k_aggregate(const float* __restrict__ xf, const uint32_t* __restrict__ xp,
                            int packed) {
    int warp = (blockIdx.x * blockDim.x + threadIdx.x) >> 5;
    int lane = threadIdx.x & 31;
    if (warp >= NN) return;
    int beg = g_rowptr[warp];
    int end = g_rowptr[warp + 1];
    float a0 = 0.f, a1 = 0.f, a2 = 0.f, a3 = 0.f;
    int j = beg;
    if (packed) {
        const uint32_t* tb = xp;
        for (; j + 3 < end; j += 4) {
            int s0 = __ldg(&g_col[j]), s1 = __ldg(&g_col[j + 1]);
            int s2 = __ldg(&g_col[j + 2]), s3 = __ldg(&g_col[j + 3]);
            uint4 v0 = *(const uint4*)(tb + (size_t)s0 * DD + lane * 4);
            uint4 v1 = *(const uint4*)(tb + (size_t)s1 * DD + lane * 4);
            uint4 v2 = *(const uint4*)(tb + (size_t)s2 * DD + lane * 4);
            uint4 v3 = *(const uint4*)(tb + (size_t)s3 * DD + lane * 4);
            a0 += unpackf(v0.x) + unpackf(v1.x) + unpackf(v2.x) + unpackf(v3.x);
            a1 += unpackf(v0.y) + unpackf(v1.y) + unpackf(v2.y) + unpackf(v3.y);
            a2 += unpackf(v0.z) + unpackf(v1.z) + unpackf(v2.z) + unpackf(v3.z);
            a3 += unpackf(v0.w) + unpackf(v1.w) + unpackf(v2.w) + unpackf(v3.w);
        }
        for (; j < end; j++) {
            int s0 = __ldg(&g_col[j]);
            uint4 v0 = *(const uint4*)(tb + (size_t)s0 * DD + lane * 4);
            a0 += unpackf(v0.x); a1 += unpackf(v0.y);
            a2 += unpackf(v0.z); a3 += unpackf(v0.w);
        }
    } else {
        const float* tb = xf;
        for (; j + 3 < end; j += 4) {
            int s0 = __ldg(&g_col[j]), s1 = __ldg(&g_col[j + 1]);
            int s2 = __ldg(&g_col[j + 2]), s3 = __ldg(&g_col[j + 3]);
            float4 v0 = *(const float4*)(tb + (size_t)s0 * DD + lane * 4);
            float4 v1 = *(const float4*)(tb + (size_t)s1 * DD + lane * 4);
            float4 v2 = *(const float4*)(tb + (size_t)s2 * DD + lane * 4);
            float4 v3 = *(const float4*)(tb + (size_t)s3 * DD + lane * 4);
            a0 += v0.x + v1.x + v2.x + v3.x;
            a1 += v0.y + v1.y + v2.y + v3.y;
            a2 += v0.z + v1.z + v2.z + v3.z;
            a3 += v0.w + v1.w + v2.w + v3.w;
        }
        for (; j < end; j++) {
            int s0 = __ldg(&g_col[j]);
            float4 v0 = *(const float4*)(tb + (size_t)s0 * DD + lane * 4);
            a0 += v0.x; a1 += v0.y; a2 += v0.z; a3 += v0.w;
        }
    }
    float id = g_invdeg[warp];
    uint4 o = make_uint4(packsplit(a0 * id), packsplit(a1 * id),
                         packsplit(a2 * id), packsplit(a3 * id));
    *(uint4*)(g_pa + (size_t)warp * DD + lane * 4) = o;
}

// ---------------- split x to packed --------------------------------------------
__global__ void k_split_x(const float* __restrict__ x) {
    int i = blockIdx.x * blockDim.x + threadIdx.x;
    if (i >= NROWS4) return;
    float4 v = ((const float4*)x)[i];
    ((uint4*)g_pk0)[i] = make_uint4(packsplit(v.x), packsplit(v.y),
                                    packsplit(v.z), packsplit(v.w));
}

// ---------------- weight transpose + bf16 split (all 3 layers) -----------------
__global__ void k_wsplit_all(const float* __restrict__ Wl0, const float* __restrict__ Wr0,
                             const float* __restrict__ Wl1, const float* __restrict__ Wr1,
                             const float* __restrict__ Wl2, const float* __restrict__ Wr2) {
    int idx = blockIdx.x * blockDim.x + threadIdx.x;
    if (idx >= 3 * 128 * 256) return;
    int l = idx >> 15;
    int r = idx & 32767;
    int k = r & 255, n = r >> 8;
    const float* Wl = (l == 0) ? Wl0 : ((l == 1) ? Wl1 : Wl2);
    const float* Wr = (l == 0) ? Wr0 : ((l == 1) ? Wr1 : Wr2);
    float w = (k < 128) ? Wl[k * 128 + n] : Wr[(k - 128) * 128 + n];
    __nv_bfloat16 h = __float2bfloat16(w);
    float rr = w - __bfloat162float(h);
    g_wt_hi[l][n * 256 + k] = h;
    g_wt_lo[l][n * 256 + k] = __float2bfloat16(rr);
}

// ---------------- HMMA GEMM + bias + LayerNorm + ELU / L2-norm -----------------
// smem: W hi/lo full-K resident (128KB) + A hi/lo double-buffered (2x32KB)
#define W_HI   0
#define W_LO   65536
#define A_HI0  131072
#define A_LO0  147456
#define A_HI1  163840
#define A_LO1  180224
#define SM_TOTAL 196608

__device__ __forceinline__ void load_chunk(uint4* pk, const uint32_t* Apk,
                                           const uint32_t* Xpk, int c, int grow,
                                           int half, bool rok) {
    if (rok) {
        const uint32_t* tb = (c < 2) ? Apk : Xpk;
        const uint4* p = (const uint4*)(tb + (size_t)grow * 128 + (c & 1) * 64 + half * 32);
#pragma unroll
        for (int q = 0; q < 8; q++) pk[q] = p[q];
    } else {
#pragma unroll
        for (int q = 0; q < 8; q++) pk[q] = make_uint4(0, 0, 0, 0);
    }
}

__global__ __launch_bounds__(256, 1)
void k_gemm_mma(const uint32_t* __restrict__ Apk, const uint32_t* __restrict__ Xpk,
                const __nv_bfloat16* __restrict__ Whi, const __nv_bfloat16* __restrict__ Wlo,
                const float* __restrict__ bl, const float* __restrict__ gg,
                const float* __restrict__ bb,
                float* __restrict__ outf, uint32_t* __restrict__ outp, int mode)
{
    extern __shared__ char smem[];
    uint32_t sb = smem_u32(smem);
    int tid = threadIdx.x;
    int wid = tid >> 5;
    int lane = tid & 31;
    int row0 = blockIdx.x * 128;
    int m0 = (wid & 3) * 32;
    int n0 = (wid >> 2) * 64;
    int t = lane & 3, g = lane >> 2;

    int srow = tid >> 1, half = tid & 1;
    uint32_t sm = (uint32_t)(srow & 7) << 4;

    // stage full-K weights (hi+lo), row stride 512B, SW within 128B groups
    {
        const uint4* ph = (const uint4*)(Whi + srow * 256 + half * 128);
        const uint4* pl = (const uint4*)(Wlo + srow * 256 + half * 128);
#pragma unroll
        for (int q = 0; q < 16; q++) {
            uint32_t off = (uint32_t)srow * 512 + (((uint32_t)(half * 256 + q * 16)) ^ sm);
            *(uint4*)(smem + W_HI + off) = ph[q];
            *(uint4*)(smem + W_LO + off) = pl[q];
        }
    }
    int grow = row0 + srow;
    bool rok = grow < NN;

    float acc[2][8][4];
#pragma unroll
    for (int mi = 0; mi < 2; mi++)
#pragma unroll
        for (int ni = 0; ni < 8; ni++)
#pragma unroll
            for (int q = 0; q < 4; q++) acc[mi][ni][q] = 0.f;

    // fragment addressing
    uint32_t swzm = (uint32_t)(lane & 7) << 4;
    uint32_t a_row = m0 + (lane & 7) + ((lane >> 3) & 1) * 8;
    uint32_t a_kb = ((lane >> 4) & 1) * 16;
    uint32_t aoff[2] = { a_row * 128u, (a_row + 16u) * 128u };
    uint32_t jj = lane >> 3;
    uint32_t b_kb = (jj & 1) * 16;
    uint32_t b_row = n0 + (jj >> 1) * 8 + (lane & 7);
    uint32_t boff[4];
#pragma unroll
    for (int p = 0; p < 4; p++) boff[p] = (b_row + p * 16u) * 512u;

    const uint32_t AHI[2] = { A_HI0, A_HI1 };
    const uint32_t ALO[2] = { A_LO0, A_LO1 };

    uint4 pk[8];
    load_chunk(pk, Apk, Xpk, 0, grow, half, rok);

    for (int c = 0; c < 4; c++) {
        uint32_t bh = AHI[c & 1], blo = ALO[c & 1];
        // unpack packed A regs -> hi/lo smem tiles
#pragma unroll
        for (int q2 = 0; q2 < 4; q2++) {
            uint4 a = pk[2 * q2], b = pk[2 * q2 + 1];
            uint4 h = make_uint4(__byte_perm(a.x, a.y, 0x5410), __byte_perm(a.z, a.w, 0x5410),
                                 __byte_perm(b.x, b.y, 0x5410), __byte_perm(b.z, b.w, 0x5410));
            uint4 l = make_uint4(__byte_perm(a.x, a.y, 0x7632), __byte_perm(a.z, a.w, 0x7632),
                                 __byte_perm(b.x, b.y, 0x7632), __byte_perm(b.z, b.w, 0x7632));
            uint32_t off = (uint32_t)srow * 128 + (((uint32_t)(half * 64 + q2 * 16)) ^ sm);
            *(uint4*)(smem + bh + off) = h;
            *(uint4*)(smem + blo + off) = l;
        }
        if (c < 3) load_chunk(pk, Apk, Xpk, c + 1, grow, half, rok);  // flies under MMA
        __syncthreads();

        uint32_t AH = sb + bh, AL = sb + blo;
#pragma unroll
        for (int ks = 0; ks < 4; ks++) {
            uint32_t kxa = ((uint32_t)(ks * 32) + a_kb) ^ swzm;
            uint32_t kxb = ((uint32_t)(c * 128 + ks * 32) + b_kb) ^ swzm;
            uint32_t ahr[2][4], alr[2][4], bhr[4][4], blr[4][4];
#pragma unroll
            for (int mi = 0; mi < 2; mi++) {
                ldm_x4(ahr[mi], AH + aoff[mi] + kxa);
                ldm_x4(alr[mi], AL + aoff[mi] + kxa);
            }
#pragma unroll
            for (int p = 0; p < 4; p++) {
                ldm_x4(bhr[p], sb + W_HI + boff[p] + kxb);
                ldm_x4(blr[p], sb + W_LO + boff[p] + kxb);
            }
#pragma unroll
            for (int mi = 0; mi < 2; mi++) {
#pragma unroll
                for (int p = 0; p < 4; p++) {
                    mma16816(acc[mi][2 * p],     ahr[mi], bhr[p][0], bhr[p][1]);
                    mma16816(acc[mi][2 * p],     ahr[mi], blr[p][0], blr[p][1]);
                    mma16816(acc[mi][2 * p],     alr[mi], bhr[p][0], bhr[p][1]);
                    mma16816(acc[mi][2 * p + 1], ahr[mi], bhr[p][2], bhr[p][3]);
                    mma16816(acc[mi][2 * p + 1], ahr[mi], blr[p][2], blr[p][3]);
                    mma16816(acc[mi][2 * p + 1], alr[mi], bhr[p][2], bhr[p][3]);
                }
            }
        }
    }
    __syncthreads();

    // ---- epilogue: bias + LN (+ELU / L2-normalize) ----
    const float2* bl2 = (const float2*)bl;
    const float2* g2 = (const float2*)gg;
    const float2* b2 = (const float2*)bb;
    float2 blv[8], gv[8], bv[8];
#pragma unroll
    for (int ni = 0; ni < 8; ni++) {
        int cp = n0 / 2 + ni * 4 + t;
        blv[ni] = __ldg(&bl2[cp]);
        gv[ni] = __ldg(&g2[cp]);
        bv[ni] = __ldg(&b2[cp]);
    }
    float s1[4] = {0, 0, 0, 0}, s2[4] = {0, 0, 0, 0};
#pragma unroll
    for (int mi = 0; mi < 2; mi++)
#pragma unroll
        for (int ni = 0; ni < 8; ni++) {
            float a0 = acc[mi][ni][0] + blv[ni].x;
            float a1 = acc[mi][ni][1] + blv[ni].y;
            float a2 = acc[mi][ni][2] + blv[ni].x;
            float a3 = acc[mi][ni][3] + blv[ni].y;
            acc[mi][ni][0] = a0; acc[mi][ni][1] = a1;
            acc[mi][ni][2] = a2; acc[mi][ni][3] = a3;
            s1[2 * mi] += a0 + a1;       s2[2 * mi] += a0 * a0 + a1 * a1;
            s1[2 * mi + 1] += a2 + a3;   s2[2 * mi + 1] += a2 * a2 + a3 * a3;
        }
#pragma unroll
    for (int q = 0; q < 4; q++) {
        s1[q] += __shfl_xor_sync(0xffffffffu, s1[q], 1);
        s1[q] += __shfl_xor_sync(0xffffffffu, s1[q], 2);
        s2[q] += __shfl_xor_sync(0xffffffffu, s2[q], 1);
        s2[q] += __shfl_xor_sync(0xffffffffu, s2[q], 2);
    }
    float2* red = (float2*)(smem + A_HI0);
    float* red2 = (float*)(smem + A_HI0 + 2048);
    int hh = wid >> 2;
    int R[4] = { m0 + g, m0 + 8 + g, m0 + 16 + g, m0 + 24 + g };
    if (t == 0) {
#pragma unroll
        for (int q = 0; q < 4; q++) red[hh * 128 + R[q]] = make_float2(s1[q], s2[q]);
    }
    __syncthreads();
    float mu[4], rs[4];
#pragma unroll
    for (int q = 0; q < 4; q++) {
        float2 o = red[(1 - hh) * 128 + R[q]];
        float t1 = s1[q] + o.x, t2 = s2[q] + o.y;
        float m = t1 * (1.0f / 128.0f);
        float var = t2 * (1.0f / 128.0f) - m * m;
        mu[q] = m;
        rs[q] = rsqrtf(var + 1e-5f);
    }
    float qs[4] = {0, 0, 0, 0};
#pragma unroll
    for (int mi = 0; mi < 2; mi++)
#pragma unroll
        for (int ni = 0; ni < 8; ni++) {
            float y0 = (acc[mi][ni][0] - mu[2 * mi]) * rs[2 * mi] * gv[ni].x + bv[ni].x;
            float y1 = (acc[mi][ni][1] - mu[2 * mi]) * rs[2 * mi] * gv[ni].y + bv[ni].y;
            float y2 = (acc[mi][ni][2] - mu[2 * mi + 1]) * rs[2 * mi + 1] * gv[ni].x + bv[ni].x;
            float y3 = (acc[mi][ni][3] - mu[2 * mi + 1]) * rs[2 * mi + 1] * gv[ni].y + bv[ni].y;
            if (mode == 0) {
                y0 = (y0 > 0.f) ? y0 : expm1f(y0);
                y1 = (y1 > 0.f) ? y1 : expm1f(y1);
                y2 = (y2 > 0.f) ? y2 : expm1f(y2);
                y3 = (y3 > 0.f) ? y3 : expm1f(y3);
            } else {
                qs[2 * mi] += y0 * y0 + y1 * y1;
                qs[2 * mi + 1] += y2 * y2 + y3 * y3;
            }
            acc[mi][ni][0] = y0; acc[mi][ni][1] = y1;
            acc[mi][ni][2] = y2; acc[mi][ni][3] = y3;
        }
    float sc[4] = {1.f, 1.f, 1.f, 1.f};
    if (mode == 1) {
#pragma unroll
        for (int q = 0; q < 4; q++) {
            qs[q] += __shfl_xor_sync(0xffffffffu, qs[q], 1);
            qs[q] += __shfl_xor_sync(0xffffffffu, qs[q], 2);
        }
        if (t == 0) {
#pragma unroll
            for (int q = 0; q < 4; q++) red2[hh * 128 + R[q]] = qs[q];
        }
        __syncthreads();
#pragma unroll
        for (int q = 0; q < 4; q++) {
            float tot = qs[q] + red2[(1 - hh) * 128 + R[q]];
            sc[q] = 1.0f / fmaxf(sqrtf(tot), 1e-12f);
        }
    }
#pragma unroll
    for (int mi = 0; mi < 2; mi++) {
        int rA = row0 + R[2 * mi];
        int rB = row0 + R[2 * mi + 1];
#pragma unroll
        for (int ni = 0; ni < 8; ni++) {
            int col = n0 + ni * 8 + t * 2;
            float y0 = acc[mi][ni][0] * sc[2 * mi];
            float y1 = acc[mi][ni][1] * sc[2 * mi];
            float y2 = acc[mi][ni][2] * sc[2 * mi + 1];
            float y3 = acc[mi][ni][3] * sc[2 * mi + 1];
            if (mode == 0) {
                if (rA < NN)
                    *(uint2*)(outp + (size_t)rA * 128 + col) =
                        make_uint2(packsplit(y0), packsplit(y1));
                if (rB < NN)
                    *(uint2*)(outp + (size_t)rB * 128 + col) =
                        make_uint2(packsplit(y2), packsplit(y3));
            } else {
                if (rA < NN)
                    *(float2*)(outf + (size_t)rA * 128 + col) = make_float2(y0, y1);
                if (rB < NN)
                    *(float2*)(outf + (size_t)rB * 128 + col) = make_float2(y2, y3);
            }
        }
    }
}

// ---------------- launch --------------------------------------------------------
extern "C" void kernel_launch(void* const* d_in, const int* in_sizes, int n_in,
                              void* d_out, int out_size) {
    const float* x = (const float*)d_in[0];
    const void* ei = d_in[1];

    uint32_t *pk0, *pk1, *pa;
    cudaGetSymbolAddress((void**)&pk0, g_pk0);
    cudaGetSymbolAddress((void**)&pk1, g_pk1);
    cudaGetSymbolAddress((void**)&pa, g_pa);
    __nv_bfloat16 *whi, *wlo;
    cudaGetSymbolAddress((void**)&whi, g_wt_hi);
    cudaGetSymbolAddress((void**)&wlo, g_wt_lo);

    cudaFuncSetAttribute(k_gemm_mma, cudaFuncAttributeMaxDynamicSharedMemorySize, SM_TOTAL);

    const int TB = 256;
    const int EBLK = (EE + TB - 1) / TB;
    const int NBLK = (NN + TB - 1) / TB;
    const int SCAN_NB = (NN + 1023) / 1024;
    const int AGG_BLK = (NN * 32 + TB - 1) / TB;
    const int GEMM_BLK = (NN + 127) / 128;

    const float* Wl0 = (const float*)d_in[2], *bl0 = (const float*)d_in[3];
    const float* Wr0 = (const float*)d_in[4], *g0 = (const float*)d_in[5], *b0 = (const float*)d_in[6];
    const float* Wl1 = (const float*)d_in[7], *bl1 = (const float*)d_in[8];
    const float* Wr1 = (const float*)d_in[9], *g1 = (const float*)d_in[10], *b1 = (const float*)d_in[11];
    const float* Wl2 = (const float*)d_in[12], *bl2 = (const float*)d_in[13];
    const float* Wr2 = (const float*)d_in[14], *g2 = (const float*)d_in[15], *b2 = (const float*)d_in[16];

    k_probe_zero<<<NBLK, TB>>>((const long long*)ei);          // 1
    k_hist<<<EBLK, TB>>>(ei);                                  // 2
    k_scan1<<<SCAN_NB, 1024>>>();                              // 3
    k_scan3b<<<NBLK, TB>>>();                                  // 4
    k_scatter<<<EBLK, TB>>>(ei);                               // 5
    k_aggregate<<<AGG_BLK, TB>>>(x, nullptr, 0);               // 6 <- ncu capture
    k_split_x<<<(NROWS4 + TB - 1) / TB, TB>>>(x);              // 7
    k_wsplit_all<<<384, TB>>>(Wl0, Wr0, Wl1, Wr1, Wl2, Wr2);   // 8

    // layer 0
    k_gemm_mma<<<GEMM_BLK, TB, SM_TOTAL>>>(pa, pk0, whi, wlo, bl0, g0, b0,
                                           nullptr, pk1, 0);
    // layer 1
    k_aggregate<<<AGG_BLK, TB>>>(nullptr, pk1, 1);
    k_gemm_mma<<<GEMM_BLK, TB, SM_TOTAL>>>(pa, pk1, whi + 32768, wlo + 32768, bl1, g1, b1,
                                           nullptr, pk0, 0);
    // layer 2
    k_aggregate<<<AGG_BLK, TB>>>(nullptr, pk0, 1);
    k_gemm_mma<<<GEMM_BLK, TB, SM_TOTAL>>>(pa, pk0, whi + 65536, wlo + 65536, bl2, g2, b2,
                                           (float*)d_out, nullptr, 1);
}

// round 5
// speedup vs baseline: 1.2863x; 1.2863x over previous
#include <cuda_runtime.h>
#include <cuda_bf16.h>
#include <math.h>
#include <cstdint>

#define NN 100000
#define EE 1600000
#define DD 128
#define NROWS4 ((NN * DD) / 4)

// ---------------- scratch (static device globals; no allocation) -------------
// packed activation: uint32 = bf16 hi (low 16) | bf16 lo (high 16); value = hi + lo
__device__ __align__(16) uint32_t g_pk0[NN * DD];
__device__ __align__(16) uint32_t g_pk1[NN * DD];
__device__ __align__(16) uint32_t g_pa [NN * DD];

__device__ int   g_col[EE];
__device__ int   g_cnt[NN];
__device__ int   g_rowptr[NN + 1];
__device__ int   g_wcur[NN];
__device__ float g_invdeg[NN];
__device__ int   g_tmp[NN];
__device__ int   g_bsum[128];
__device__ int   g_is64;

// pre-split transposed weights per layer: [n=128][k=256] bf16 hi/lo
__device__ __align__(16) __nv_bfloat16 g_wt_hi[3][128 * 256];
__device__ __align__(16) __nv_bfloat16 g_wt_lo[3][128 * 256];

// ================= helpers =====================================================
__device__ __forceinline__ uint32_t smem_u32(const void* p) {
    uint32_t a;
    asm("{ .reg .u64 t; cvta.to.shared.u64 t, %1; cvt.u32.u64 %0, t; }" : "=r"(a) : "l"(p));
    return a;
}
__device__ __forceinline__ void ldm_x4(uint32_t* r, uint32_t addr) {
    asm volatile("ldmatrix.sync.aligned.m8n8.x4.shared.b16 {%0,%1,%2,%3}, [%4];"
                 : "=r"(r[0]), "=r"(r[1]), "=r"(r[2]), "=r"(r[3]) : "r"(addr));
}
__device__ __forceinline__ void mma16816(float* c, const uint32_t* a, uint32_t b0, uint32_t b1) {
    asm volatile(
        "mma.sync.aligned.m16n8k16.row.col.f32.bf16.bf16.f32 "
        "{%0,%1,%2,%3},{%4,%5,%6,%7},{%8,%9},{%0,%1,%2,%3};"
        : "+f"(c[0]), "+f"(c[1]), "+f"(c[2]), "+f"(c[3])
        : "r"(a[0]), "r"(a[1]), "r"(a[2]), "r"(a[3]), "r"(b0), "r"(b1));
}
__device__ __forceinline__ void cp_async16(uint32_t dst, const void* src) {
    asm volatile("cp.async.cg.shared.global [%0], [%1], 16;" :: "r"(dst), "l"(src) : "memory");
}
__device__ __forceinline__ uint32_t packsplit(float a) {
    __nv_bfloat16 h = __float2bfloat16(a);
    float r = a - __bfloat162float(h);
    __nv_bfloat16 l = __float2bfloat16(r);
    return (uint32_t)__bfloat16_as_ushort(h) | ((uint32_t)__bfloat16_as_ushort(l) << 16);
}
__device__ __forceinline__ float unpackf(uint32_t p) {
    return __uint_as_float(p << 16) + __uint_as_float(p & 0xffff0000u);
}

// ---------------- CSR build (fused) --------------------------------------------
__global__ void k_probe_zero(const long long* __restrict__ p) {
    int i = blockIdx.x * blockDim.x + threadIdx.x;
    if (i < NN) g_cnt[i] = 0;
    if (blockIdx.x == 0) {
        long long v = p[threadIdx.x];
        int bad = (v < 0 || v >= NN) ? 1 : 0;
        unsigned m = __ballot_sync(0xffffffffu, bad);
        __shared__ int any;
        if (threadIdx.x == 0) any = 0;
        __syncthreads();
        if ((threadIdx.x & 31) == 0 && m) atomicOr(&any, 1);
        __syncthreads();
        if (threadIdx.x == 0) g_is64 = any ? 0 : 1;
    }
}
__global__ void k_hist(const void* __restrict__ ei) {
    int e = blockIdx.x * blockDim.x + threadIdx.x;
    if (e >= EE) return;
    int d = g_is64 ? (int)((const long long*)ei)[EE + e] : ((const int*)ei)[EE + e];
    atomicAdd(&g_cnt[d], 1);
}
__global__ void k_scan1() {
    __shared__ int s[1024];
    int tid = threadIdx.x;
    int gid = blockIdx.x * 1024 + tid;
    int v = (gid < NN) ? g_cnt[gid] : 0;
    s[tid] = v;
    __syncthreads();
    for (int off = 1; off < 1024; off <<= 1) {
        int t = (tid >= off) ? s[tid - off] : 0;
        __syncthreads();
        s[tid] += t;
        __syncthreads();
    }
    int incl = s[tid];
    if (gid < NN) g_tmp[gid] = incl - v;
    if (tid == 1023) g_bsum[blockIdx.x] = incl;
}
__global__ void k_scan3b() {
    __shared__ int base;
    int sbk = blockIdx.x >> 2;
    if (threadIdx.x < 32) {
        int a = 0;
        for (int i = threadIdx.x; i < sbk; i += 32) a += g_bsum[i];
#pragma unroll
        for (int o = 16; o > 0; o >>= 1) a += __shfl_xor_sync(0xffffffffu, a, o);
        if (threadIdx.x == 0) base = a;
    }
    __syncthreads();
    int i = blockIdx.x * 256 + threadIdx.x;
    if (i < NN) {
        int rp = g_tmp[i] + base;
        g_rowptr[i] = rp;
        g_wcur[i] = rp;
        int c = g_cnt[i];
        g_invdeg[i] = 1.0f / (float)(c > 1 ? c : 1);
        if (i == 0) g_rowptr[NN] = EE;
    }
}
__global__ void k_scatter(const void* __restrict__ ei) {
    int e = blockIdx.x * blockDim.x + threadIdx.x;
    if (e >= EE) return;
    int s, d;
    if (g_is64) {
        const long long* p = (const long long*)ei;
        s = (int)p[e]; d = (int)p[EE + e];
    } else {
        const int* p = (const int*)ei;
        s = p[e]; d = p[EE + e];
    }
    g_col[atomicAdd(&g_wcur[d], 1)] = s;
}

// ---------------- mean aggregation: one warp per node, packed out -------------
__global__ void k_aggregate(const float* __restrict__ xf, const uint32_t* __restrict__ xp,
                            int packed) {
    int warp = (blockIdx.x * blockDim.x + threadIdx.x) >> 5;
    int lane = threadIdx.x & 31;
    if (warp >= NN) return;
    int beg = g_rowptr[warp];
    int end = g_rowptr[warp + 1];
    float a0 = 0.f, a1 = 0.f, a2 = 0.f, a3 = 0.f;
    int j = beg;
    if (packed) {
        const uint32_t* tb = xp;
        for (; j + 3 < end; j += 4) {
            int s0 = __ldg(&g_col[j]), s1 = __ldg(&g_col[j + 1]);
            int s2 = __ldg(&g_col[j + 2]), s3 = __ldg(&g_col[j + 3]);
            uint4 v0 = *(const uint4*)(tb + (size_t)s0 * DD + lane * 4);
            uint4 v1 = *(const uint4*)(tb + (size_t)s1 * DD + lane * 4);
            uint4 v2 = *(const uint4*)(tb + (size_t)s2 * DD + lane * 4);
            uint4 v3 = *(const uint4*)(tb + (size_t)s3 * DD + lane * 4);
            a0 += unpackf(v0.x) + unpackf(v1.x) + unpackf(v2.x) + unpackf(v3.x);
            a1 += unpackf(v0.y) + unpackf(v1.y) + unpackf(v2.y) + unpackf(v3.y);
            a2 += unpackf(v0.z) + unpackf(v1.z) + unpackf(v2.z) + unpackf(v3.z);
            a3 += unpackf(v0.w) + unpackf(v1.w) + unpackf(v2.w) + unpackf(v3.w);
        }
        for (; j < end; j++) {
            int s0 = __ldg(&g_col[j]);
            uint4 v0 = *(const uint4*)(tb + (size_t)s0 * DD + lane * 4);
            a0 += unpackf(v0.x); a1 += unpackf(v0.y);
            a2 += unpackf(v0.z); a3 += unpackf(v0.w);
        }
    } else {
        const float* tb = xf;
        for (; j + 3 < end; j += 4) {
            int s0 = __ldg(&g_col[j]), s1 = __ldg(&g_col[j + 1]);
            int s2 = __ldg(&g_col[j + 2]), s3 = __ldg(&g_col[j + 3]);
            float4 v0 = *(const float4*)(tb + (size_t)s0 * DD + lane * 4);
            float4 v1 = *(const float4*)(tb + (size_t)s1 * DD + lane * 4);
            float4 v2 = *(const float4*)(tb + (size_t)s2 * DD + lane * 4);
            float4 v3 = *(const float4*)(tb + (size_t)s3 * DD + lane * 4);
            a0 += v0.x + v1.x + v2.x + v3.x;
            a1 += v0.y + v1.y + v2.y + v3.y;
            a2 += v0.z + v1.z + v2.z + v3.z;
            a3 += v0.w + v1.w + v2.w + v3.w;
        }
        for (; j < end; j++) {
            int s0 = __ldg(&g_col[j]);
            float4 v0 = *(const float4*)(tb + (size_t)s0 * DD + lane * 4);
            a0 += v0.x; a1 += v0.y; a2 += v0.z; a3 += v0.w;
        }
    }
    float id = g_invdeg[warp];
    uint4 o = make_uint4(packsplit(a0 * id), packsplit(a1 * id),
                         packsplit(a2 * id), packsplit(a3 * id));
    *(uint4*)(g_pa + (size_t)warp * DD + lane * 4) = o;
}

// ---------------- split x to packed --------------------------------------------
__global__ void k_split_x(const float* __restrict__ x) {
    int i = blockIdx.x * blockDim.x + threadIdx.x;
    if (i >= NROWS4) return;
    float4 v = ((const float4*)x)[i];
    ((uint4*)g_pk0)[i] = make_uint4(packsplit(v.x), packsplit(v.y),
                                    packsplit(v.z), packsplit(v.w));
}

// ---------------- weight transpose + bf16 split (all 3 layers) -----------------
__global__ void k_wsplit_all(const float* __restrict__ Wl0, const float* __restrict__ Wr0,
                             const float* __restrict__ Wl1, const float* __restrict__ Wr1,
                             const float* __restrict__ Wl2, const float* __restrict__ Wr2) {
    int idx = blockIdx.x * blockDim.x + threadIdx.x;
    if (idx >= 3 * 128 * 256) return;
    int l = idx >> 15;
    int r = idx & 32767;
    int k = r & 255, n = r >> 8;
    const float* Wl = (l == 0) ? Wl0 : ((l == 1) ? Wl1 : Wl2);
    const float* Wr = (l == 0) ? Wr0 : ((l == 1) ? Wr1 : Wr2);
    float w = (k < 128) ? Wl[k * 128 + n] : Wr[(k - 128) * 128 + n];
    __nv_bfloat16 h = __float2bfloat16(w);
    float rr = w - __bfloat162float(h);
    g_wt_hi[l][n * 256 + k] = h;
    g_wt_lo[l][n * 256 + k] = __float2bfloat16(rr);
}

// ---------------- HMMA GEMM + bias + LayerNorm + ELU / L2-norm -----------------
// 64KB smem: per-chunk A hi/lo + W hi/lo tiles (128x64 bf16 each)
#define AS_HI 0
#define AS_LO 16384
#define WS_HI 32768
#define WS_LO 49152
#define SM_TOTAL 65536

__global__ __launch_bounds__(256, 2)
void k_gemm_mma(const uint32_t* __restrict__ Apk, const uint32_t* __restrict__ Xpk,
                const __nv_bfloat16* __restrict__ Whi, const __nv_bfloat16* __restrict__ Wlo,
                const float* __restrict__ bl, const float* __restrict__ gg,
                const float* __restrict__ bb,
                float* __restrict__ outf, uint32_t* __restrict__ outp, int mode)
{
    extern __shared__ char smem[];
    uint32_t sb = smem_u32(smem);
    int tid = threadIdx.x;
    int wid = tid >> 5;
    int lane = tid & 31;
    int row0 = blockIdx.x * 128;
    int m0 = (wid & 3) * 32;
    int n0 = (wid >> 2) * 64;
    int t = lane & 3, g = lane >> 2;

    float acc[2][8][4];
#pragma unroll
    for (int mi = 0; mi < 2; mi++)
#pragma unroll
        for (int ni = 0; ni < 8; ni++)
#pragma unroll
            for (int q = 0; q < 4; q++) acc[mi][ni][q] = 0.f;

    // fragment addressing (row stride 128B for both tiles)
    uint32_t swzm = (uint32_t)(lane & 7) << 4;
    uint32_t a_row = m0 + (lane & 7) + ((lane >> 3) & 1) * 8;
    uint32_t a_kb = ((lane >> 4) & 1) * 16;
    uint32_t aoff[2] = { a_row * 128u, (a_row + 16u) * 128u };
    uint32_t jj = lane >> 3;
    uint32_t b_kb = (jj & 1) * 16;
    uint32_t b_row = n0 + (jj >> 1) * 8 + (lane & 7);
    uint32_t boff[4];
#pragma unroll
    for (int p = 0; p < 4; p++) boff[p] = (b_row + p * 16u) * 128u;

    // staging mapping
    int srow = tid >> 1, half = tid & 1;
    uint32_t sm = (uint32_t)(srow & 7) << 4;
    int grow = row0 + srow;
    bool rok = grow < NN;
    uint32_t rb = (uint32_t)srow * 128u;

    for (int c = 0; c < 4; c++) {
        if (c) __syncthreads();
        // ---- W tiles via cp.async (no registers, overlaps A unpack) ----
        {
            const __nv_bfloat16* pwh = Whi + srow * 256 + c * 64 + half * 32;
            const __nv_bfloat16* pwl = Wlo + srow * 256 + c * 64 + half * 32;
#pragma unroll
            for (int q = 0; q < 4; q++) {
                uint32_t off = rb + (((uint32_t)(half * 64 + q * 16)) ^ sm);
                cp_async16(sb + WS_HI + off, pwh + q * 8);
                cp_async16(sb + WS_LO + off, pwl + q * 8);
            }
            asm volatile("cp.async.commit_group;" ::: "memory");
        }
        // ---- A: packed load + unpack to hi/lo ----
        {
            const uint32_t* tb = (c < 2) ? Apk : Xpk;
            uint4 pk[8];
            if (rok) {
                const uint4* p = (const uint4*)(tb + (size_t)grow * 128 + (c & 1) * 64 + half * 32);
#pragma unroll
                for (int q = 0; q < 8; q++) pk[q] = p[q];
            } else {
#pragma unroll
                for (int q = 0; q < 8; q++) pk[q] = make_uint4(0, 0, 0, 0);
            }
#pragma unroll
            for (int q2 = 0; q2 < 4; q2++) {
                uint4 a = pk[2 * q2], b = pk[2 * q2 + 1];
                uint4 h = make_uint4(__byte_perm(a.x, a.y, 0x5410), __byte_perm(a.z, a.w, 0x5410),
                                     __byte_perm(b.x, b.y, 0x5410), __byte_perm(b.z, b.w, 0x5410));
                uint4 l = make_uint4(__byte_perm(a.x, a.y, 0x7632), __byte_perm(a.z, a.w, 0x7632),
                                     __byte_perm(b.x, b.y, 0x7632), __byte_perm(b.z, b.w, 0x7632));
                uint32_t off = rb + (((uint32_t)(half * 64 + q2 * 16)) ^ sm);
                *(uint4*)(smem + AS_HI + off) = h;
                *(uint4*)(smem + AS_LO + off) = l;
            }
        }
        asm volatile("cp.async.wait_group 0;" ::: "memory");
        __syncthreads();

#pragma unroll
        for (int ks = 0; ks < 4; ks++) {
            uint32_t kxa = ((uint32_t)(ks * 32) + a_kb) ^ swzm;
            uint32_t kxb = ((uint32_t)(ks * 32) + b_kb) ^ swzm;
            uint32_t ahr[2][4], alr[2][4], bhr[4][4], blr[4][4];
#pragma unroll
            for (int mi = 0; mi < 2; mi++) {
                ldm_x4(ahr[mi], sb + AS_HI + aoff[mi] + kxa);
                ldm_x4(alr[mi], sb + AS_LO + aoff[mi] + kxa);
            }
#pragma unroll
            for (int p = 0; p < 4; p++) {
                ldm_x4(bhr[p], sb + WS_HI + boff[p] + kxb);
                ldm_x4(blr[p], sb + WS_LO + boff[p] + kxb);
            }
#pragma unroll
            for (int mi = 0; mi < 2; mi++) {
#pragma unroll
                for (int p = 0; p < 4; p++) {
                    mma16816(acc[mi][2 * p],     ahr[mi], bhr[p][0], bhr[p][1]);
                    mma16816(acc[mi][2 * p],     ahr[mi], blr[p][0], blr[p][1]);
                    mma16816(acc[mi][2 * p],     alr[mi], bhr[p][0], bhr[p][1]);
                    mma16816(acc[mi][2 * p + 1], ahr[mi], bhr[p][2], bhr[p][3]);
                    mma16816(acc[mi][2 * p + 1], ahr[mi], blr[p][2], blr[p][3]);
                    mma16816(acc[mi][2 * p + 1], alr[mi], bhr[p][2], bhr[p][3]);
                }
            }
        }
    }
    __syncthreads();   // tiles dead; smem reused for reductions

    // ---- epilogue: bias + LN (+ELU / L2-normalize) ----
    const float2* bl2 = (const float2*)bl;
    const float2* g2 = (const float2*)gg;
    const float2* b2 = (const float2*)bb;
    float2 blv[8], gv[8], bv[8];
#pragma unroll
    for (int ni = 0; ni < 8; ni++) {
        int cp = n0 / 2 + ni * 4 + t;
        blv[ni] = __ldg(&bl2[cp]);
        gv[ni] = __ldg(&g2[cp]);
        bv[ni] = __ldg(&b2[cp]);
    }
    float s1[4] = {0, 0, 0, 0}, s2[4] = {0, 0, 0, 0};
#pragma unroll
    for (int mi = 0; mi < 2; mi++)
#pragma unroll
        for (int ni = 0; ni < 8; ni++) {
            float a0 = acc[mi][ni][0] + blv[ni].x;
            float a1 = acc[mi][ni][1] + blv[ni].y;
            float a2 = acc[mi][ni][2] + blv[ni].x;
            float a3 = acc[mi][ni][3] + blv[ni].y;
            acc[mi][ni][0] = a0; acc[mi][ni][1] = a1;
            acc[mi][ni][2] = a2; acc[mi][ni][3] = a3;
            s1[2 * mi] += a0 + a1;       s2[2 * mi] += a0 * a0 + a1 * a1;
            s1[2 * mi + 1] += a2 + a3;   s2[2 * mi + 1] += a2 * a2 + a3 * a3;
        }
#pragma unroll
    for (int q = 0; q < 4; q++) {
        s1[q] += __shfl_xor_sync(0xffffffffu, s1[q], 1);
        s1[q] += __shfl_xor_sync(0xffffffffu, s1[q], 2);
        s2[q] += __shfl_xor_sync(0xffffffffu, s2[q], 1);
        s2[q] += __shfl_xor_sync(0xffffffffu, s2[q], 2);
    }
    float2* red = (float2*)smem;
    float* red2 = (float*)(smem + 2048);
    int hh = wid >> 2;
    int R[4] = { m0 + g, m0 + 8 + g, m0 + 16 + g, m0 + 24 + g };
    if (t == 0) {
#pragma unroll
        for (int q = 0; q < 4; q++) red[hh * 128 + R[q]] = make_float2(s1[q], s2[q]);
    }
    __syncthreads();
    float mu[4], rs[4];
#pragma unroll
    for (int q = 0; q < 4; q++) {
        float2 o = red[(1 - hh) * 128 + R[q]];
        float t1 = s1[q] + o.x, t2 = s2[q] + o.y;
        float m = t1 * (1.0f / 128.0f);
        float var = t2 * (1.0f / 128.0f) - m * m;
        mu[q] = m;
        rs[q] = rsqrtf(var + 1e-5f);
    }
    float qs[4] = {0, 0, 0, 0};
#pragma unroll
    for (int mi = 0; mi < 2; mi++)
#pragma unroll
        for (int ni = 0; ni < 8; ni++) {
            float y0 = (acc[mi][ni][0] - mu[2 * mi]) * rs[2 * mi] * gv[ni].x + bv[ni].x;
            float y1 = (acc[mi][ni][1] - mu[2 * mi]) * rs[2 * mi] * gv[ni].y + bv[ni].y;
            float y2 = (acc[mi][ni][2] - mu[2 * mi + 1]) * rs[2 * mi + 1] * gv[ni].x + bv[ni].x;
            float y3 = (acc[mi][ni][3] - mu[2 * mi + 1]) * rs[2 * mi + 1] * gv[ni].y + bv[ni].y;
            if (mode == 0) {
                y0 = (y0 > 0.f) ? y0 : expm1f(y0);
                y1 = (y1 > 0.f) ? y1 : expm1f(y1);
                y2 = (y2 > 0.f) ? y2 : expm1f(y2);
                y3 = (y3 > 0.f) ? y3 : expm1f(y3);
            } else {
                qs[2 * mi] += y0 * y0 + y1 * y1;
                qs[2 * mi + 1] += y2 * y2 + y3 * y3;
            }
            acc[mi][ni][0] = y0; acc[mi][ni][1] = y1;
            acc[mi][ni][2] = y2; acc[mi][ni][3] = y3;
        }
    float sc[4] = {1.f, 1.f, 1.f, 1.f};
    if (mode == 1) {
#pragma unroll
        for (int q = 0; q < 4; q++) {
            qs[q] += __shfl_xor_sync(0xffffffffu, qs[q], 1);
            qs[q] += __shfl_xor_sync(0xffffffffu, qs[q], 2);
        }
        if (t == 0) {
#pragma unroll
            for (int q = 0; q < 4; q++) red2[hh * 128 + R[q]] = qs[q];
        }
        __syncthreads();
#pragma unroll
        for (int q = 0; q < 4; q++) {
            float tot = qs[q] + red2[(1 - hh) * 128 + R[q]];
            sc[q] = 1.0f / fmaxf(sqrtf(tot), 1e-12f);
        }
    }
#pragma unroll
    for (int mi = 0; mi < 2; mi++) {
        int rA = row0 + R[2 * mi];
        int rB = row0 + R[2 * mi + 1];
#pragma unroll
        for (int ni = 0; ni < 8; ni++) {
            int col = n0 + ni * 8 + t * 2;
            float y0 = acc[mi][ni][0] * sc[2 * mi];
            float y1 = acc[mi][ni][1] * sc[2 * mi];
            float y2 = acc[mi][ni][2] * sc[2 * mi + 1];
            float y3 = acc[mi][ni][3] * sc[2 * mi + 1];
            if (mode == 0) {
                if (rA < NN)
                    *(uint2*)(outp + (size_t)rA * 128 + col) =
                        make_uint2(packsplit(y0), packsplit(y1));
                if (rB < NN)
                    *(uint2*)(outp + (size_t)rB * 128 + col) =
                        make_uint2(packsplit(y2), packsplit(y3));
            } else {
                if (rA < NN)
                    *(float2*)(outf + (size_t)rA * 128 + col) = make_float2(y0, y1);
                if (rB < NN)
                    *(float2*)(outf + (size_t)rB * 128 + col) = make_float2(y2, y3);
            }
        }
    }
}

// ---------------- launch --------------------------------------------------------
extern "C" void kernel_launch(void* const* d_in, const int* in_sizes, int n_in,
                              void* d_out, int out_size) {
    const float* x = (const float*)d_in[0];
    const void* ei = d_in[1];

    uint32_t *pk0, *pk1, *pa;
    cudaGetSymbolAddress((void**)&pk0, g_pk0);
    cudaGetSymbolAddress((void**)&pk1, g_pk1);
    cudaGetSymbolAddress((void**)&pa, g_pa);
    __nv_bfloat16 *whi, *wlo;
    cudaGetSymbolAddress((void**)&whi, g_wt_hi);
    cudaGetSymbolAddress((void**)&wlo, g_wt_lo);

    cudaFuncSetAttribute(k_gemm_mma, cudaFuncAttributeMaxDynamicSharedMemorySize, SM_TOTAL);

    const int TB = 256;
    const int EBLK = (EE + TB - 1) / TB;
    const int NBLK = (NN + TB - 1) / TB;
    const int SCAN_NB = (NN + 1023) / 1024;
    const int AGG_BLK = (NN * 32 + TB - 1) / TB;
    const int GEMM_BLK = (NN + 127) / 128;

    const float* Wl0 = (const float*)d_in[2], *bl0 = (const float*)d_in[3];
    const float* Wr0 = (const float*)d_in[4], *g0 = (const float*)d_in[5], *b0 = (const float*)d_in[6];
    const float* Wl1 = (const float*)d_in[7], *bl1 = (const float*)d_in[8];
    const float* Wr1 = (const float*)d_in[9], *g1 = (const float*)d_in[10], *b1 = (const float*)d_in[11];
    const float* Wl2 = (const float*)d_in[12], *bl2 = (const float*)d_in[13];
    const float* Wr2 = (const float*)d_in[14], *g2 = (const float*)d_in[15], *b2 = (const float*)d_in[16];

    k_probe_zero<<<NBLK, TB>>>((const long long*)ei);
    k_hist<<<EBLK, TB>>>(ei);
    k_scan1<<<SCAN_NB, 1024>>>();
    k_scan3b<<<NBLK, TB>>>();
    k_scatter<<<EBLK, TB>>>(ei);
    k_aggregate<<<AGG_BLK, TB>>>(x, nullptr, 0);
    k_split_x<<<(NROWS4 + TB - 1) / TB, TB>>>(x);
    k_wsplit_all<<<384, TB>>>(Wl0, Wr0, Wl1, Wr1, Wl2, Wr2);

    // layer 0
    k_gemm_mma<<<GEMM_BLK, TB, SM_TOTAL>>>(pa, pk0, whi, wlo, bl0, g0, b0,
                                           nullptr, pk1, 0);
    // layer 1
    k_aggregate<<<AGG_BLK, TB>>>(nullptr, pk1, 1);
    k_gemm_mma<<<GEMM_BLK, TB, SM_TOTAL>>>(pa, pk1, whi + 32768, wlo + 32768, bl1, g1, b1,
                                           nullptr, pk0, 0);
    // layer 2
    k_aggregate<<<AGG_BLK, TB>>>(nullptr, pk0, 1);
    k_gemm_mma<<<GEMM_BLK, TB, SM_TOTAL>>>(pa, pk0, whi + 65536, wlo + 65536, bl2, g2, b2,
                                           (float*)d_out, nullptr, 1);
}

// round 6
// speedup vs baseline: 1.3668x; 1.0626x over previous
#include <cuda_runtime.h>
#include <cuda_bf16.h>
#include <cuda_fp16.h>
#include <math.h>
#include <cstdint>

#define NN 100000
#define EE 1600000
#define DD 128
#define NROWS4 ((NN * DD) / 4)

// ---------------- scratch (static device globals; no allocation) -------------
// packed activation: uint32 = bf16 hi (low 16) | bf16 lo (high 16); value = hi + lo
__device__ __align__(16) uint32_t g_pk0[NN * DD];
__device__ __align__(16) uint32_t g_pk1[NN * DD];
__device__ __align__(16) uint32_t g_pa [NN * DD];
__device__ __align__(16) __half   g_f16[NN * DD];   // fp16 copy for gather

__device__ int   g_col[EE];
__device__ int   g_cnt[NN];
__device__ int   g_rowptr[NN + 1];
__device__ int   g_wcur[NN];
__device__ float g_invdeg[NN];
__device__ int   g_tmp[NN];
__device__ int   g_bsum[128];
__device__ int   g_is64;

// pre-split transposed weights per layer: [n=128][k=256] bf16 hi/lo
__device__ __align__(16) __nv_bfloat16 g_wt_hi[3][128 * 256];
__device__ __align__(16) __nv_bfloat16 g_wt_lo[3][128 * 256];

// ================= helpers =====================================================
__device__ __forceinline__ uint32_t smem_u32(const void* p) {
    uint32_t a;
    asm("{ .reg .u64 t; cvta.to.shared.u64 t, %1; cvt.u32.u64 %0, t; }" : "=r"(a) : "l"(p));
    return a;
}
__device__ __forceinline__ void ldm_x4(uint32_t* r, uint32_t addr) {
    asm volatile("ldmatrix.sync.aligned.m8n8.x4.shared.b16 {%0,%1,%2,%3}, [%4];"
                 : "=r"(r[0]), "=r"(r[1]), "=r"(r[2]), "=r"(r[3]) : "r"(addr));
}
__device__ __forceinline__ void mma16816(float* c, const uint32_t* a, uint32_t b0, uint32_t b1) {
    asm volatile(
        "mma.sync.aligned.m16n8k16.row.col.f32.bf16.bf16.f32 "
        "{%0,%1,%2,%3},{%4,%5,%6,%7},{%8,%9},{%0,%1,%2,%3};"
        : "+f"(c[0]), "+f"(c[1]), "+f"(c[2]), "+f"(c[3])
        : "r"(a[0]), "r"(a[1]), "r"(a[2]), "r"(a[3]), "r"(b0), "r"(b1));
}
__device__ __forceinline__ void cp_async16(uint32_t dst, const void* src) {
    asm volatile("cp.async.cg.shared.global [%0], [%1], 16;" :: "r"(dst), "l"(src) : "memory");
}
__device__ __forceinline__ uint32_t packsplit(float a) {
    __nv_bfloat16 h = __float2bfloat16(a);
    float r = a - __bfloat162float(h);
    __nv_bfloat16 l = __float2bfloat16(r);
    return (uint32_t)__bfloat16_as_ushort(h) | ((uint32_t)__bfloat16_as_ushort(l) << 16);
}
__device__ __forceinline__ uint32_t packh2(float a, float b) {
    __half2 h = __floats2half2_rn(a, b);
    return *(uint32_t*)&h;
}

// ---------------- init: split x + zero cnt + dtype probe -----------------------
__global__ void k_init(const float* __restrict__ x, const long long* __restrict__ p) {
    int i = blockIdx.x * blockDim.x + threadIdx.x;
    if (i < NROWS4) {
        float4 v = ((const float4*)x)[i];
        ((uint4*)g_pk0)[i] = make_uint4(packsplit(v.x), packsplit(v.y),
                                        packsplit(v.z), packsplit(v.w));
        ((uint2*)g_f16)[i] = make_uint2(packh2(v.x, v.y), packh2(v.z, v.w));
    }
    if (i < NN) g_cnt[i] = 0;
    if (blockIdx.x == 0) {
        long long v = p[threadIdx.x];
        int bad = (v < 0 || v >= NN) ? 1 : 0;
        unsigned m = __ballot_sync(0xffffffffu, bad);
        __shared__ int any;
        if (threadIdx.x == 0) any = 0;
        __syncthreads();
        if ((threadIdx.x & 31) == 0 && m) atomicOr(&any, 1);
        __syncthreads();
        if (threadIdx.x == 0) g_is64 = any ? 0 : 1;
    }
}

// ---------------- CSR build -----------------------------------------------------
__global__ void k_hist(const void* __restrict__ ei) {
    int e = blockIdx.x * blockDim.x + threadIdx.x;
    if (e >= EE) return;
    int d = g_is64 ? (int)((const long long*)ei)[EE + e] : ((const int*)ei)[EE + e];
    atomicAdd(&g_cnt[d], 1);
}
__global__ void k_scan1() {
    __shared__ int s[1024];
    int tid = threadIdx.x;
    int gid = blockIdx.x * 1024 + tid;
    int v = (gid < NN) ? g_cnt[gid] : 0;
    s[tid] = v;
    __syncthreads();
    for (int off = 1; off < 1024; off <<= 1) {
        int t = (tid >= off) ? s[tid - off] : 0;
        __syncthreads();
        s[tid] += t;
        __syncthreads();
    }
    int incl = s[tid];
    if (gid < NN) g_tmp[gid] = incl - v;
    if (tid == 1023) g_bsum[blockIdx.x] = incl;
}
__global__ void k_scan3b() {
    __shared__ int base;
    int sbk = blockIdx.x >> 2;
    if (threadIdx.x < 32) {
        int a = 0;
        for (int i = threadIdx.x; i < sbk; i += 32) a += g_bsum[i];
#pragma unroll
        for (int o = 16; o > 0; o >>= 1) a += __shfl_xor_sync(0xffffffffu, a, o);
        if (threadIdx.x == 0) base = a;
    }
    __syncthreads();
    int i = blockIdx.x * 256 + threadIdx.x;
    if (i < NN) {
        int rp = g_tmp[i] + base;
        g_rowptr[i] = rp;
        g_wcur[i] = rp;
        int c = g_cnt[i];
        g_invdeg[i] = 1.0f / (float)(c > 1 ? c : 1);
        if (i == 0) g_rowptr[NN] = EE;
    }
}
__global__ void k_scatter(const void* __restrict__ ei) {
    int e = blockIdx.x * blockDim.x + threadIdx.x;
    if (e >= EE) return;
    int s, d;
    if (g_is64) {
        const long long* p = (const long long*)ei;
        s = (int)p[e]; d = (int)p[EE + e];
    } else {
        const int* p = (const int*)ei;
        s = p[e]; d = p[EE + e];
    }
    g_col[atomicAdd(&g_wcur[d], 1)] = s;
}

// ---------------- mean aggregation: one warp per node, fp16 gather ------------
__global__ void k_aggregate() {
    int warp = (blockIdx.x * blockDim.x + threadIdx.x) >> 5;
    int lane = threadIdx.x & 31;
    if (warp >= NN) return;
    int beg = g_rowptr[warp];
    int end = g_rowptr[warp + 1];
    float a0 = 0.f, a1 = 0.f, a2 = 0.f, a3 = 0.f;
    const __half* tb = g_f16;
    int j = beg;
    for (; j + 3 < end; j += 4) {
        int s0 = __ldg(&g_col[j]), s1 = __ldg(&g_col[j + 1]);
        int s2 = __ldg(&g_col[j + 2]), s3 = __ldg(&g_col[j + 3]);
        uint2 v0 = *(const uint2*)(tb + (size_t)s0 * DD + lane * 4);
        uint2 v1 = *(const uint2*)(tb + (size_t)s1 * DD + lane * 4);
        uint2 v2 = *(const uint2*)(tb + (size_t)s2 * DD + lane * 4);
        uint2 v3 = *(const uint2*)(tb + (size_t)s3 * DD + lane * 4);
        float2 p;
        p = __half22float2(*(__half2*)&v0.x); a0 += p.x; a1 += p.y;
        p = __half22float2(*(__half2*)&v0.y); a2 += p.x; a3 += p.y;
        p = __half22float2(*(__half2*)&v1.x); a0 += p.x; a1 += p.y;
        p = __half22float2(*(__half2*)&v1.y); a2 += p.x; a3 += p.y;
        p = __half22float2(*(__half2*)&v2.x); a0 += p.x; a1 += p.y;
        p = __half22float2(*(__half2*)&v2.y); a2 += p.x; a3 += p.y;
        p = __half22float2(*(__half2*)&v3.x); a0 += p.x; a1 += p.y;
        p = __half22float2(*(__half2*)&v3.y); a2 += p.x; a3 += p.y;
    }
    for (; j < end; j++) {
        int s0 = __ldg(&g_col[j]);
        uint2 v0 = *(const uint2*)(tb + (size_t)s0 * DD + lane * 4);
        float2 p;
        p = __half22float2(*(__half2*)&v0.x); a0 += p.x; a1 += p.y;
        p = __half22float2(*(__half2*)&v0.y); a2 += p.x; a3 += p.y;
    }
    float id = g_invdeg[warp];
    uint4 o = make_uint4(packsplit(a0 * id), packsplit(a1 * id),
                         packsplit(a2 * id), packsplit(a3 * id));
    *(uint4*)(g_pa + (size_t)warp * DD + lane * 4) = o;
}

// ---------------- weight transpose + bf16 split (all 3 layers) -----------------
__global__ void k_wsplit_all(const float* __restrict__ Wl0, const float* __restrict__ Wr0,
                             const float* __restrict__ Wl1, const float* __restrict__ Wr1,
                             const float* __restrict__ Wl2, const float* __restrict__ Wr2) {
    int idx = blockIdx.x * blockDim.x + threadIdx.x;
    if (idx >= 3 * 128 * 256) return;
    int l = idx >> 15;
    int r = idx & 32767;
    int k = r & 255, n = r >> 8;
    const float* Wl = (l == 0) ? Wl0 : ((l == 1) ? Wl1 : Wl2);
    const float* Wr = (l == 0) ? Wr0 : ((l == 1) ? Wr1 : Wr2);
    float w = (k < 128) ? Wl[k * 128 + n] : Wr[(k - 128) * 128 + n];
    __nv_bfloat16 h = __float2bfloat16(w);
    float rr = w - __bfloat162float(h);
    g_wt_hi[l][n * 256 + k] = h;
    g_wt_lo[l][n * 256 + k] = __float2bfloat16(rr);
}

// ---------------- HMMA GEMM + bias + LayerNorm + ELU / L2-norm -----------------
#define AS_HI 0
#define AS_LO 16384
#define WS_HI 32768
#define WS_LO 49152
#define SM_TOTAL 65536

__global__ __launch_bounds__(256, 2)
void k_gemm_mma(const uint32_t* __restrict__ Apk, const uint32_t* __restrict__ Xpk,
                const __nv_bfloat16* __restrict__ Whi, const __nv_bfloat16* __restrict__ Wlo,
                const float* __restrict__ bl, const float* __restrict__ gg,
                const float* __restrict__ bb,
                float* __restrict__ outf, uint32_t* __restrict__ outp, int mode)
{
    extern __shared__ char smem[];
    uint32_t sb = smem_u32(smem);
    int tid = threadIdx.x;
    int wid = tid >> 5;
    int lane = tid & 31;
    int row0 = blockIdx.x * 128;
    int m0 = (wid & 3) * 32;
    int n0 = (wid >> 2) * 64;
    int t = lane & 3, g = lane >> 2;

    float acc[2][8][4];
#pragma unroll
    for (int mi = 0; mi < 2; mi++)
#pragma unroll
        for (int ni = 0; ni < 8; ni++)
#pragma unroll
            for (int q = 0; q < 4; q++) acc[mi][ni][q] = 0.f;

    uint32_t swzm = (uint32_t)(lane & 7) << 4;
    uint32_t a_row = m0 + (lane & 7) + ((lane >> 3) & 1) * 8;
    uint32_t a_kb = ((lane >> 4) & 1) * 16;
    uint32_t aoff[2] = { a_row * 128u, (a_row + 16u) * 128u };
    uint32_t jj = lane >> 3;
    uint32_t b_kb = (jj & 1) * 16;
    uint32_t b_row = n0 + (jj >> 1) * 8 + (lane & 7);
    uint32_t boff[4];
#pragma unroll
    for (int p = 0; p < 4; p++) boff[p] = (b_row + p * 16u) * 128u;

    int srow = tid >> 1, half = tid & 1;
    uint32_t sm = (uint32_t)(srow & 7) << 4;
    int grow = row0 + srow;
    bool rok = grow < NN;
    uint32_t rb = (uint32_t)srow * 128u;

    for (int c = 0; c < 4; c++) {
        if (c) __syncthreads();
        {
            const __nv_bfloat16* pwh = Whi + srow * 256 + c * 64 + half * 32;
            const __nv_bfloat16* pwl = Wlo + srow * 256 + c * 64 + half * 32;
#pragma unroll
            for (int q = 0; q < 4; q++) {
                uint32_t off = rb + (((uint32_t)(half * 64 + q * 16)) ^ sm);
                cp_async16(sb + WS_HI + off, pwh + q * 8);
                cp_async16(sb + WS_LO + off, pwl + q * 8);
            }
            asm volatile("cp.async.commit_group;" ::: "memory");
        }
        {
            const uint32_t* tb = (c < 2) ? Apk : Xpk;
            uint4 pk[8];
            if (rok) {
                const uint4* p = (const uint4*)(tb + (size_t)grow * 128 + (c & 1) * 64 + half * 32);
#pragma unroll
                for (int q = 0; q < 8; q++) pk[q] = p[q];
            } else {
#pragma unroll
                for (int q = 0; q < 8; q++) pk[q] = make_uint4(0, 0, 0, 0);
            }
#pragma unroll
            for (int q2 = 0; q2 < 4; q2++) {
                uint4 a = pk[2 * q2], b = pk[2 * q2 + 1];
                uint4 h = make_uint4(__byte_perm(a.x, a.y, 0x5410), __byte_perm(a.z, a.w, 0x5410),
                                     __byte_perm(b.x, b.y, 0x5410), __byte_perm(b.z, b.w, 0x5410));
                uint4 l = make_uint4(__byte_perm(a.x, a.y, 0x7632), __byte_perm(a.z, a.w, 0x7632),
                                     __byte_perm(b.x, b.y, 0x7632), __byte_perm(b.z, b.w, 0x7632));
                uint32_t off = rb + (((uint32_t)(half * 64 + q2 * 16)) ^ sm);
                *(uint4*)(smem + AS_HI + off) = h;
                *(uint4*)(smem + AS_LO + off) = l;
            }
        }
        asm volatile("cp.async.wait_group 0;" ::: "memory");
        __syncthreads();

#pragma unroll
        for (int ks = 0; ks < 4; ks++) {
            uint32_t kxa = ((uint32_t)(ks * 32) + a_kb) ^ swzm;
            uint32_t kxb = ((uint32_t)(ks * 32) + b_kb) ^ swzm;
            uint32_t ahr[2][4], alr[2][4], bhr[4][4], blr[4][4];
#pragma unroll
            for (int mi = 0; mi < 2; mi++) {
                ldm_x4(ahr[mi], sb + AS_HI + aoff[mi] + kxa);
                ldm_x4(alr[mi], sb + AS_LO + aoff[mi] + kxa);
            }
#pragma unroll
            for (int p = 0; p < 4; p++) {
                ldm_x4(bhr[p], sb + WS_HI + boff[p] + kxb);
                ldm_x4(blr[p], sb + WS_LO + boff[p] + kxb);
            }
#pragma unroll
            for (int mi = 0; mi < 2; mi++) {
#pragma unroll
                for (int p = 0; p < 4; p++) {
                    mma16816(acc[mi][2 * p],     ahr[mi], bhr[p][0], bhr[p][1]);
                    mma16816(acc[mi][2 * p],     ahr[mi], blr[p][0], blr[p][1]);
                    mma16816(acc[mi][2 * p],     alr[mi], bhr[p][0], bhr[p][1]);
                    mma16816(acc[mi][2 * p + 1], ahr[mi], bhr[p][2], bhr[p][3]);
                    mma16816(acc[mi][2 * p + 1], ahr[mi], blr[p][2], blr[p][3]);
                    mma16816(acc[mi][2 * p + 1], alr[mi], bhr[p][2], bhr[p][3]);
                }
            }
        }
    }
    __syncthreads();

    // ---- epilogue ----
    const float2* bl2 = (const float2*)bl;
    const float2* g2 = (const float2*)gg;
    const float2* b2 = (const float2*)bb;
    float2 blv[8], gv[8], bv[8];
#pragma unroll
    for (int ni = 0; ni < 8; ni++) {
        int cp = n0 / 2 + ni * 4 + t;
        blv[ni] = __ldg(&bl2[cp]);
        gv[ni] = __ldg(&g2[cp]);
        bv[ni] = __ldg(&b2[cp]);
    }
    float s1[4] = {0, 0, 0, 0}, s2[4] = {0, 0, 0, 0};
#pragma unroll
    for (int mi = 0; mi < 2; mi++)
#pragma unroll
        for (int ni = 0; ni < 8; ni++) {
            float a0 = acc[mi][ni][0] + blv[ni].x;
            float a1 = acc[mi][ni][1] + blv[ni].y;
            float a2 = acc[mi][ni][2] + blv[ni].x;
            float a3 = acc[mi][ni][3] + blv[ni].y;
            acc[mi][ni][0] = a0; acc[mi][ni][1] = a1;
            acc[mi][ni][2] = a2; acc[mi][ni][3] = a3;
            s1[2 * mi] += a0 + a1;       s2[2 * mi] += a0 * a0 + a1 * a1;
            s1[2 * mi + 1] += a2 + a3;   s2[2 * mi + 1] += a2 * a2 + a3 * a3;
        }
#pragma unroll
    for (int q = 0; q < 4; q++) {
        s1[q] += __shfl_xor_sync(0xffffffffu, s1[q], 1);
        s1[q] += __shfl_xor_sync(0xffffffffu, s1[q], 2);
        s2[q] += __shfl_xor_sync(0xffffffffu, s2[q], 1);
        s2[q] += __shfl_xor_sync(0xffffffffu, s2[q], 2);
    }
    float2* red = (float2*)smem;
    float* red2 = (float*)(smem + 2048);
    int hh = wid >> 2;
    int R[4] = { m0 + g, m0 + 8 + g, m0 + 16 + g, m0 + 24 + g };
    if (t == 0) {
#pragma unroll
        for (int q = 0; q < 4; q++) red[hh * 128 + R[q]] = make_float2(s1[q], s2[q]);
    }
    __syncthreads();
    float mu[4], rs[4];
#pragma unroll
    for (int q = 0; q < 4; q++) {
        float2 o = red[(1 - hh) * 128 + R[q]];
        float t1 = s1[q] + o.x, t2 = s2[q] + o.y;
        float m = t1 * (1.0f / 128.0f);
        float var = t2 * (1.0f / 128.0f) - m * m;
        mu[q] = m;
        rs[q] = rsqrtf(var + 1e-5f);
    }
    float qs[4] = {0, 0, 0, 0};
#pragma unroll
    for (int mi = 0; mi < 2; mi++)
#pragma unroll
        for (int ni = 0; ni < 8; ni++) {
            float y0 = (acc[mi][ni][0] - mu[2 * mi]) * rs[2 * mi] * gv[ni].x + bv[ni].x;
            float y1 = (acc[mi][ni][1] - mu[2 * mi]) * rs[2 * mi] * gv[ni].y + bv[ni].y;
            float y2 = (acc[mi][ni][2] - mu[2 * mi + 1]) * rs[2 * mi + 1] * gv[ni].x + bv[ni].x;
            float y3 = (acc[mi][ni][3] - mu[2 * mi + 1]) * rs[2 * mi + 1] * gv[ni].y + bv[ni].y;
            if (mode == 0) {
                y0 = (y0 > 0.f) ? y0 : expm1f(y0);
                y1 = (y1 > 0.f) ? y1 : expm1f(y1);
                y2 = (y2 > 0.f) ? y2 : expm1f(y2);
                y3 = (y3 > 0.f) ? y3 : expm1f(y3);
            } else {
                qs[2 * mi] += y0 * y0 + y1 * y1;
                qs[2 * mi + 1] += y2 * y2 + y3 * y3;
            }
            acc[mi][ni][0] = y0; acc[mi][ni][1] = y1;
            acc[mi][ni][2] = y2; acc[mi][ni][3] = y3;
        }
    float sc[4] = {1.f, 1.f, 1.f, 1.f};
    if (mode == 1) {
#pragma unroll
        for (int q = 0; q < 4; q++) {
            qs[q] += __shfl_xor_sync(0xffffffffu, qs[q], 1);
            qs[q] += __shfl_xor_sync(0xffffffffu, qs[q], 2);
        }
        if (t == 0) {
#pragma unroll
            for (int q = 0; q < 4; q++) red2[hh * 128 + R[q]] = qs[q];
        }
        __syncthreads();
#pragma unroll
        for (int q = 0; q < 4; q++) {
            float tot = qs[q] + red2[(1 - hh) * 128 + R[q]];
            sc[q] = 1.0f / fmaxf(sqrtf(tot), 1e-12f);
        }
    }
#pragma unroll
    for (int mi = 0; mi < 2; mi++) {
        int rA = row0 + R[2 * mi];
        int rB = row0 + R[2 * mi + 1];
#pragma unroll
        for (int ni = 0; ni < 8; ni++) {
            int col = n0 + ni * 8 + t * 2;
            float y0 = acc[mi][ni][0] * sc[2 * mi];
            float y1 = acc[mi][ni][1] * sc[2 * mi];
            float y2 = acc[mi][ni][2] * sc[2 * mi + 1];
            float y3 = acc[mi][ni][3] * sc[2 * mi + 1];
            if (mode == 0) {
                if (rA < NN) {
                    *(uint2*)(outp + (size_t)rA * 128 + col) =
                        make_uint2(packsplit(y0), packsplit(y1));
                    *(uint32_t*)((__half*)g_f16 + (size_t)rA * 128 + col) = packh2(y0, y1);
                }
                if (rB < NN) {
                    *(uint2*)(outp + (size_t)rB * 128 + col) =
                        make_uint2(packsplit(y2), packsplit(y3));
                    *(uint32_t*)((__half*)g_f16 + (size_t)rB * 128 + col) = packh2(y2, y3);
                }
            } else {
                if (rA < NN)
                    *(float2*)(outf + (size_t)rA * 128 + col) = make_float2(y0, y1);
                if (rB < NN)
                    *(float2*)(outf + (size_t)rB * 128 + col) = make_float2(y2, y3);
            }
        }
    }
}

// ---------------- launch --------------------------------------------------------
extern "C" void kernel_launch(void* const* d_in, const int* in_sizes, int n_in,
                              void* d_out, int out_size) {
    const float* x = (const float*)d_in[0];
    const void* ei = d_in[1];

    uint32_t *pk0, *pk1, *pa;
    cudaGetSymbolAddress((void**)&pk0, g_pk0);
    cudaGetSymbolAddress((void**)&pk1, g_pk1);
    cudaGetSymbolAddress((void**)&pa, g_pa);
    __nv_bfloat16 *whi, *wlo;
    cudaGetSymbolAddress((void**)&whi, g_wt_hi);
    cudaGetSymbolAddress((void**)&wlo, g_wt_lo);

    cudaFuncSetAttribute(k_gemm_mma, cudaFuncAttributeMaxDynamicSharedMemorySize, SM_TOTAL);

    const int TB = 256;
    const int EBLK = (EE + TB - 1) / TB;
    const int SCAN_NB = (NN + 1023) / 1024;
    const int NBLK = (NN + TB - 1) / TB;
    const int AGG_BLK = (NN * 32 + TB - 1) / TB;
    const int GEMM_BLK = (NN + 127) / 128;

    const float* Wl0 = (const float*)d_in[2], *bl0 = (const float*)d_in[3];
    const float* Wr0 = (const float*)d_in[4], *g0 = (const float*)d_in[5], *b0 = (const float*)d_in[6];
    const float* Wl1 = (const float*)d_in[7], *bl1 = (const float*)d_in[8];
    const float* Wr1 = (const float*)d_in[9], *g1 = (const float*)d_in[10], *b1 = (const float*)d_in[11];
    const float* Wl2 = (const float*)d_in[12], *bl2 = (const float*)d_in[13];
    const float* Wr2 = (const float*)d_in[14], *g2 = (const float*)d_in[15], *b2 = (const float*)d_in[16];

    k_init<<<(NROWS4 + TB - 1) / TB, TB>>>(x, (const long long*)ei);  // 1
    k_hist<<<EBLK, TB>>>(ei);                                         // 2
    k_scan1<<<SCAN_NB, 1024>>>();                                     // 3
    k_scan3b<<<NBLK, TB>>>();                                         // 4
    k_scatter<<<EBLK, TB>>>(ei);                                      // 5
    k_aggregate<<<AGG_BLK, TB>>>();                                   // 6 <- ncu capture
    k_wsplit_all<<<384, TB>>>(Wl0, Wr0, Wl1, Wr1, Wl2, Wr2);          // 7

    // layer 0  (gemm writes pk1 + f16)
    k_gemm_mma<<<GEMM_BLK, TB, SM_TOTAL>>>(pa, pk0, whi, wlo, bl0, g0, b0,
                                           nullptr, pk1, 0);
    // layer 1
    k_aggregate<<<AGG_BLK, TB>>>();
    k_gemm_mma<<<GEMM_BLK, TB, SM_TOTAL>>>(pa, pk1, whi + 32768, wlo + 32768, bl1, g1, b1,
                                           nullptr, pk0, 0);
    // layer 2
    k_aggregate<<<AGG_BLK, TB>>>();
    k_gemm_mma<<<GEMM_BLK, TB, SM_TOTAL>>>(pa, pk0, whi + 65536, wlo + 65536, bl2, g2, b2,
                                           (float*)d_out, nullptr, 1);
}

// round 7
// speedup vs baseline: 1.7598x; 1.2875x over previous
#include <cuda_runtime.h>
#include <cuda_fp16.h>
#include <math.h>
#include <cstdint>

#define NN 100000
#define EE 1600000
#define DD 128
#define NROWS4 ((NN * DD) / 4)

// ---------------- scratch (static device globals; no allocation) -------------
__device__ __align__(16) __half g_t0[NN * DD];     // activation ping (starts as x)
__device__ __align__(16) __half g_t1[NN * DD];     // activation pong
__device__ __align__(16) __half g_agg16[NN * DD];  // mean aggregate

__device__ int   g_col[EE];
__device__ int   g_cnt[NN];
__device__ int   g_rowptr[NN + 1];
__device__ int   g_wcur[NN];
__device__ float g_invdeg[NN];
__device__ int   g_tmp[NN];
__device__ int   g_bsum[128];
__device__ int   g_is64;

// pre-split transposed weights per layer: [n=128][k=256] fp16 hi/lo (exact 2-term)
__device__ __align__(16) __half g_wt_hi[3][128 * 256];
__device__ __align__(16) __half g_wt_lo[3][128 * 256];

// ================= helpers =====================================================
__device__ __forceinline__ uint32_t smem_u32(const void* p) {
    uint32_t a;
    asm("{ .reg .u64 t; cvta.to.shared.u64 t, %1; cvt.u32.u64 %0, t; }" : "=r"(a) : "l"(p));
    return a;
}
__device__ __forceinline__ void ldm_x4(uint32_t* r, uint32_t addr) {
    asm volatile("ldmatrix.sync.aligned.m8n8.x4.shared.b16 {%0,%1,%2,%3}, [%4];"
                 : "=r"(r[0]), "=r"(r[1]), "=r"(r[2]), "=r"(r[3]) : "r"(addr));
}
__device__ __forceinline__ void mma16816(float* c, const uint32_t* a, uint32_t b0, uint32_t b1) {
    asm volatile(
        "mma.sync.aligned.m16n8k16.row.col.f32.f16.f16.f32 "
        "{%0,%1,%2,%3},{%4,%5,%6,%7},{%8,%9},{%0,%1,%2,%3};"
        : "+f"(c[0]), "+f"(c[1]), "+f"(c[2]), "+f"(c[3])
        : "r"(a[0]), "r"(a[1]), "r"(a[2]), "r"(a[3]), "r"(b0), "r"(b1));
}
__device__ __forceinline__ void cp_async16z(uint32_t dst, const void* src, int ok) {
    // zero-fills when ok==0 (src-size 0)
    asm volatile("cp.async.cg.shared.global [%0], [%1], 16, %2;"
                 :: "r"(dst), "l"(src), "r"(ok ? 16 : 0) : "memory");
}
__device__ __forceinline__ uint32_t packh2(float a, float b) {
    __half2 h = __floats2half2_rn(a, b);
    return *(uint32_t*)&h;
}

// ---------------- init: x -> fp16 + zero cnt + dtype probe ---------------------
__global__ void k_init(const float* __restrict__ x, const long long* __restrict__ p) {
    int i = blockIdx.x * blockDim.x + threadIdx.x;
    if (i < NROWS4) {
        float4 v = ((const float4*)x)[i];
        ((uint2*)g_t0)[i] = make_uint2(packh2(v.x, v.y), packh2(v.z, v.w));
    }
    if (i < NN) g_cnt[i] = 0;
    if (blockIdx.x == 0) {
        long long v = p[threadIdx.x];
        int bad = (v < 0 || v >= NN) ? 1 : 0;
        unsigned m = __ballot_sync(0xffffffffu, bad);
        __shared__ int any;
        if (threadIdx.x == 0) any = 0;
        __syncthreads();
        if ((threadIdx.x & 31) == 0 && m) atomicOr(&any, 1);
        __syncthreads();
        if (threadIdx.x == 0) g_is64 = any ? 0 : 1;
    }
}

// ---------------- CSR build -----------------------------------------------------
__global__ void k_hist(const void* __restrict__ ei) {
    int e = blockIdx.x * blockDim.x + threadIdx.x;
    if (e >= EE) return;
    int d = g_is64 ? (int)((const long long*)ei)[EE + e] : ((const int*)ei)[EE + e];
    atomicAdd(&g_cnt[d], 1);
}
__global__ void k_scan1() {
    __shared__ int s[1024];
    int tid = threadIdx.x;
    int gid = blockIdx.x * 1024 + tid;
    int v = (gid < NN) ? g_cnt[gid] : 0;
    s[tid] = v;
    __syncthreads();
    for (int off = 1; off < 1024; off <<= 1) {
        int t = (tid >= off) ? s[tid - off] : 0;
        __syncthreads();
        s[tid] += t;
        __syncthreads();
    }
    int incl = s[tid];
    if (gid < NN) g_tmp[gid] = incl - v;
    if (tid == 1023) g_bsum[blockIdx.x] = incl;
}
__global__ void k_scan3b() {
    __shared__ int base;
    int sbk = blockIdx.x >> 2;
    if (threadIdx.x < 32) {
        int a = 0;
        for (int i = threadIdx.x; i < sbk; i += 32) a += g_bsum[i];
#pragma unroll
        for (int o = 16; o > 0; o >>= 1) a += __shfl_xor_sync(0xffffffffu, a, o);
        if (threadIdx.x == 0) base = a;
    }
    __syncthreads();
    int i = blockIdx.x * 256 + threadIdx.x;
    if (i < NN) {
        int rp = g_tmp[i] + base;
        g_rowptr[i] = rp;
        g_wcur[i] = rp;
        int c = g_cnt[i];
        g_invdeg[i] = 1.0f / (float)(c > 1 ? c : 1);
        if (i == 0) g_rowptr[NN] = EE;
    }
}
__global__ void k_scatter(const void* __restrict__ ei) {
    int e = blockIdx.x * blockDim.x + threadIdx.x;
    if (e >= EE) return;
    int s, d;
    if (g_is64) {
        const long long* p = (const long long*)ei;
        s = (int)p[e]; d = (int)p[EE + e];
    } else {
        const int* p = (const int*)ei;
        s = p[e]; d = p[EE + e];
    }
    g_col[atomicAdd(&g_wcur[d], 1)] = s;
}

// ---------------- mean aggregation: one warp per node, fp16 in/out -------------
__global__ void k_aggregate(const __half* __restrict__ tb) {
    int warp = (blockIdx.x * blockDim.x + threadIdx.x) >> 5;
    int lane = threadIdx.x & 31;
    if (warp >= NN) return;
    int beg = g_rowptr[warp];
    int end = g_rowptr[warp + 1];
    float a0 = 0.f, a1 = 0.f, a2 = 0.f, a3 = 0.f;
    int j = beg;
    for (; j + 3 < end; j += 4) {
        int s0 = __ldg(&g_col[j]), s1 = __ldg(&g_col[j + 1]);
        int s2 = __ldg(&g_col[j + 2]), s3 = __ldg(&g_col[j + 3]);
        uint2 v0 = *(const uint2*)(tb + (size_t)s0 * DD + lane * 4);
        uint2 v1 = *(const uint2*)(tb + (size_t)s1 * DD + lane * 4);
        uint2 v2 = *(const uint2*)(tb + (size_t)s2 * DD + lane * 4);
        uint2 v3 = *(const uint2*)(tb + (size_t)s3 * DD + lane * 4);
        float2 p;
        p = __half22float2(*(__half2*)&v0.x); a0 += p.x; a1 += p.y;
        p = __half22float2(*(__half2*)&v0.y); a2 += p.x; a3 += p.y;
        p = __half22float2(*(__half2*)&v1.x); a0 += p.x; a1 += p.y;
        p = __half22float2(*(__half2*)&v1.y); a2 += p.x; a3 += p.y;
        p = __half22float2(*(__half2*)&v2.x); a0 += p.x; a1 += p.y;
        p = __half22float2(*(__half2*)&v2.y); a2 += p.x; a3 += p.y;
        p = __half22float2(*(__half2*)&v3.x); a0 += p.x; a1 += p.y;
        p = __half22float2(*(__half2*)&v3.y); a2 += p.x; a3 += p.y;
    }
    for (; j < end; j++) {
        int s0 = __ldg(&g_col[j]);
        uint2 v0 = *(const uint2*)(tb + (size_t)s0 * DD + lane * 4);
        float2 p;
        p = __half22float2(*(__half2*)&v0.x); a0 += p.x; a1 += p.y;
        p = __half22float2(*(__half2*)&v0.y); a2 += p.x; a3 += p.y;
    }
    float id = g_invdeg[warp];
    *(uint2*)(g_agg16 + (size_t)warp * DD + lane * 4) =
        make_uint2(packh2(a0 * id, a1 * id), packh2(a2 * id, a3 * id));
}

// ---------------- weight transpose + fp16 split (all 3 layers) -----------------
__global__ void k_wsplit_all(const float* __restrict__ Wl0, const float* __restrict__ Wr0,
                             const float* __restrict__ Wl1, const float* __restrict__ Wr1,
                             const float* __restrict__ Wl2, const float* __restrict__ Wr2) {
    int idx = blockIdx.x * blockDim.x + threadIdx.x;
    if (idx >= 3 * 128 * 256) return;
    int l = idx >> 15;
    int r = idx & 32767;
    int k = r & 255, n = r >> 8;
    const float* Wl = (l == 0) ? Wl0 : ((l == 1) ? Wl1 : Wl2);
    const float* Wr = (l == 0) ? Wr0 : ((l == 1) ? Wr1 : Wr2);
    float w = (k < 128) ? Wl[k * 128 + n] : Wr[(k - 128) * 128 + n];
    __half h = __float2half_rn(w);
    float rr = w - __half2float(h);
    g_wt_hi[l][n * 256 + k] = h;
    g_wt_lo[l][n * 256 + k] = __float2half_rn(rr);
}

// ---------------- HMMA GEMM + bias + LayerNorm + ELU / L2-norm -----------------
// 48KB smem: A fp16 + W hi fp16 + W lo fp16 (each 128x64 = 16KB)
#define AS_T  0
#define WS_HI 16384
#define WS_LO 32768
#define SM_TOTAL 49152

__global__ __launch_bounds__(256, 2)
void k_gemm_mma(const __half* __restrict__ Agg, const __half* __restrict__ X,
                const __half* __restrict__ Whi, const __half* __restrict__ Wlo,
                const float* __restrict__ bl, const float* __restrict__ gg,
                const float* __restrict__ bb,
                float* __restrict__ outf, __half* __restrict__ outh, int mode)
{
    extern __shared__ char smem[];
    uint32_t sb = smem_u32(smem);
    int tid = threadIdx.x;
    int wid = tid >> 5;
    int lane = tid & 31;
    int row0 = blockIdx.x * 128;
    int m0 = (wid & 3) * 32;
    int n0 = (wid >> 2) * 64;
    int t = lane & 3, g = lane >> 2;

    float acc[2][8][4];
#pragma unroll
    for (int mi = 0; mi < 2; mi++)
#pragma unroll
        for (int ni = 0; ni < 8; ni++)
#pragma unroll
            for (int q = 0; q < 4; q++) acc[mi][ni][q] = 0.f;

    // fragment addressing (both tiles: 128 rows x 64 fp16, 128B rows, swizzled)
    uint32_t swzm = (uint32_t)(lane & 7) << 4;
    uint32_t a_row = m0 + (lane & 7) + ((lane >> 3) & 1) * 8;
    uint32_t a_kb = ((lane >> 4) & 1) * 16;
    uint32_t aoff[2] = { a_row * 128u, (a_row + 16u) * 128u };
    uint32_t jj = lane >> 3;
    uint32_t b_kb = (jj & 1) * 16;
    uint32_t b_row = n0 + (jj >> 1) * 8 + (lane & 7);
    uint32_t boff[4];
#pragma unroll
    for (int p = 0; p < 4; p++) boff[p] = (b_row + p * 16u) * 128u;

    // staging mapping: thread -> (row, 32-elem half)
    int srow = tid >> 1, half = tid & 1;
    uint32_t sm = (uint32_t)(srow & 7) << 4;
    int grow = row0 + srow;
    int rok = grow < NN;
    int grc = rok ? grow : 0;
    uint32_t rb = (uint32_t)srow * 128u;

    for (int c = 0; c < 4; c++) {
        if (c) __syncthreads();
        {
            const __half* pa = ((c < 2) ? Agg : X) + (size_t)grc * 128 + (c & 1) * 64 + half * 32;
            const __half* pwh = Whi + srow * 256 + c * 64 + half * 32;
            const __half* pwl = Wlo + srow * 256 + c * 64 + half * 32;
#pragma unroll
            for (int q = 0; q < 4; q++) {
                uint32_t off = rb + (((uint32_t)(half * 64 + q * 16)) ^ sm);
                cp_async16z(sb + AS_T + off, pa + q * 8, rok);
                cp_async16z(sb + WS_HI + off, pwh + q * 8, 1);
                cp_async16z(sb + WS_LO + off, pwl + q * 8, 1);
            }
            asm volatile("cp.async.commit_group;" ::: "memory");
            asm volatile("cp.async.wait_group 0;" ::: "memory");
        }
        __syncthreads();

#pragma unroll
        for (int ks = 0; ks < 4; ks++) {
            uint32_t kxa = ((uint32_t)(ks * 32) + a_kb) ^ swzm;
            uint32_t kxb = ((uint32_t)(ks * 32) + b_kb) ^ swzm;
            uint32_t ar[2][4], bhr[4][4], blr[4][4];
#pragma unroll
            for (int mi = 0; mi < 2; mi++)
                ldm_x4(ar[mi], sb + AS_T + aoff[mi] + kxa);
#pragma unroll
            for (int p = 0; p < 4; p++) {
                ldm_x4(bhr[p], sb + WS_HI + boff[p] + kxb);
                ldm_x4(blr[p], sb + WS_LO + boff[p] + kxb);
            }
#pragma unroll
            for (int mi = 0; mi < 2; mi++) {
#pragma unroll
                for (int p = 0; p < 4; p++) {
                    mma16816(acc[mi][2 * p],     ar[mi], bhr[p][0], bhr[p][1]);
                    mma16816(acc[mi][2 * p],     ar[mi], blr[p][0], blr[p][1]);
                    mma16816(acc[mi][2 * p + 1], ar[mi], bhr[p][2], bhr[p][3]);
                    mma16816(acc[mi][2 * p + 1], ar[mi], blr[p][2], blr[p][3]);
                }
            }
        }
    }
    __syncthreads();   // tiles dead; smem reused for reductions

    // ---- epilogue: bias + LN (+ELU / L2-normalize) ----
    const float2* bl2 = (const float2*)bl;
    const float2* g2 = (const float2*)gg;
    const float2* b2 = (const float2*)bb;
    float2 blv[8], gv[8], bv[8];
#pragma unroll
    for (int ni = 0; ni < 8; ni++) {
        int cp = n0 / 2 + ni * 4 + t;
        blv[ni] = __ldg(&bl2[cp]);
        gv[ni] = __ldg(&g2[cp]);
        bv[ni] = __ldg(&b2[cp]);
    }
    float s1[4] = {0, 0, 0, 0}, s2[4] = {0, 0, 0, 0};
#pragma unroll
    for (int mi = 0; mi < 2; mi++)
#pragma unroll
        for (int ni = 0; ni < 8; ni++) {
            float a0 = acc[mi][ni][0] + blv[ni].x;
            float a1 = acc[mi][ni][1] + blv[ni].y;
            float a2 = acc[mi][ni][2] + blv[ni].x;
            float a3 = acc[mi][ni][3] + blv[ni].y;
            acc[mi][ni][0] = a0; acc[mi][ni][1] = a1;
            acc[mi][ni][2] = a2; acc[mi][ni][3] = a3;
            s1[2 * mi] += a0 + a1;       s2[2 * mi] += a0 * a0 + a1 * a1;
            s1[2 * mi + 1] += a2 + a3;   s2[2 * mi + 1] += a2 * a2 + a3 * a3;
        }
#pragma unroll
    for (int q = 0; q < 4; q++) {
        s1[q] += __shfl_xor_sync(0xffffffffu, s1[q], 1);
        s1[q] += __shfl_xor_sync(0xffffffffu, s1[q], 2);
        s2[q] += __shfl_xor_sync(0xffffffffu, s2[q], 1);
        s2[q] += __shfl_xor_sync(0xffffffffu, s2[q], 2);
    }
    float2* red = (float2*)smem;
    float* red2 = (float*)(smem + 2048);
    int hh = wid >> 2;
    int R[4] = { m0 + g, m0 + 8 + g, m0 + 16 + g, m0 + 24 + g };
    if (t == 0) {
#pragma unroll
        for (int q = 0; q < 4; q++) red[hh * 128 + R[q]] = make_float2(s1[q], s2[q]);
    }
    __syncthreads();
    float mu[4], rs[4];
#pragma unroll
    for (int q = 0; q < 4; q++) {
        float2 o = red[(1 - hh) * 128 + R[q]];
        float t1 = s1[q] + o.x, t2 = s2[q] + o.y;
        float m = t1 * (1.0f / 128.0f);
        float var = t2 * (1.0f / 128.0f) - m * m;
        mu[q] = m;
        rs[q] = rsqrtf(var + 1e-5f);
    }
    float qs[4] = {0, 0, 0, 0};
#pragma unroll
    for (int mi = 0; mi < 2; mi++)
#pragma unroll
        for (int ni = 0; ni < 8; ni++) {
            float y0 = (acc[mi][ni][0] - mu[2 * mi]) * rs[2 * mi] * gv[ni].x + bv[ni].x;
            float y1 = (acc[mi][ni][1] - mu[2 * mi]) * rs[2 * mi] * gv[ni].y + bv[ni].y;
            float y2 = (acc[mi][ni][2] - mu[2 * mi + 1]) * rs[2 * mi + 1] * gv[ni].x + bv[ni].x;
            float y3 = (acc[mi][ni][3] - mu[2 * mi + 1]) * rs[2 * mi + 1] * gv[ni].y + bv[ni].y;
            if (mode == 0) {
                y0 = (y0 > 0.f) ? y0 : expm1f(y0);
                y1 = (y1 > 0.f) ? y1 : expm1f(y1);
                y2 = (y2 > 0.f) ? y2 : expm1f(y2);
                y3 = (y3 > 0.f) ? y3 : expm1f(y3);
            } else {
                qs[2 * mi] += y0 * y0 + y1 * y1;
                qs[2 * mi + 1] += y2 * y2 + y3 * y3;
            }
            acc[mi][ni][0] = y0; acc[mi][ni][1] = y1;
            acc[mi][ni][2] = y2; acc[mi][ni][3] = y3;
        }
    float sc[4] = {1.f, 1.f, 1.f, 1.f};
    if (mode == 1) {
#pragma unroll
        for (int q = 0; q < 4; q++) {
            qs[q] += __shfl_xor_sync(0xffffffffu, qs[q], 1);
            qs[q] += __shfl_xor_sync(0xffffffffu, qs[q], 2);
        }
        if (t == 0) {
#pragma unroll
            for (int q = 0; q < 4; q++) red2[hh * 128 + R[q]] = qs[q];
        }
        __syncthreads();
#pragma unroll
        for (int q = 0; q < 4; q++) {
            float tot = qs[q] + red2[(1 - hh) * 128 + R[q]];
            sc[q] = 1.0f / fmaxf(sqrtf(tot), 1e-12f);
        }
    }
#pragma unroll
    for (int mi = 0; mi < 2; mi++) {
        int rA = row0 + R[2 * mi];
        int rB = row0 + R[2 * mi + 1];
#pragma unroll
        for (int ni = 0; ni < 8; ni++) {
            int col = n0 + ni * 8 + t * 2;
            float y0 = acc[mi][ni][0] * sc[2 * mi];
            float y1 = acc[mi][ni][1] * sc[2 * mi];
            float y2 = acc[mi][ni][2] * sc[2 * mi + 1];
            float y3 = acc[mi][ni][3] * sc[2 * mi + 1];
            if (mode == 0) {
                if (rA < NN)
                    *(uint32_t*)(outh + (size_t)rA * 128 + col) = packh2(y0, y1);
                if (rB < NN)
                    *(uint32_t*)(outh + (size_t)rB * 128 + col) = packh2(y2, y3);
            } else {
                if (rA < NN)
                    *(float2*)(outf + (size_t)rA * 128 + col) = make_float2(y0, y1);
                if (rB < NN)
                    *(float2*)(outf + (size_t)rB * 128 + col) = make_float2(y2, y3);
            }
        }
    }
}

// ---------------- launch --------------------------------------------------------
extern "C" void kernel_launch(void* const* d_in, const int* in_sizes, int n_in,
                              void* d_out, int out_size) {
    const float* x = (const float*)d_in[0];
    const void* ei = d_in[1];

    __half *t0, *t1, *agg16, *whi, *wlo;
    cudaGetSymbolAddress((void**)&t0, g_t0);
    cudaGetSymbolAddress((void**)&t1, g_t1);
    cudaGetSymbolAddress((void**)&agg16, g_agg16);
    cudaGetSymbolAddress((void**)&whi, g_wt_hi);
    cudaGetSymbolAddress((void**)&wlo, g_wt_lo);

    cudaFuncSetAttribute(k_gemm_mma, cudaFuncAttributeMaxDynamicSharedMemorySize, SM_TOTAL);

    const int TB = 256;
    const int EBLK = (EE + TB - 1) / TB;
    const int SCAN_NB = (NN + 1023) / 1024;
    const int NBLK = (NN + TB - 1) / TB;
    const int AGG_BLK = (NN * 32 + TB - 1) / TB;
    const int GEMM_BLK = (NN + 127) / 128;

    const float* Wl0 = (const float*)d_in[2], *bl0 = (const float*)d_in[3];
    const float* Wr0 = (const float*)d_in[4], *g0 = (const float*)d_in[5], *b0 = (const float*)d_in[6];
    const float* Wl1 = (const float*)d_in[7], *bl1 = (const float*)d_in[8];
    const float* Wr1 = (const float*)d_in[9], *g1 = (const float*)d_in[10], *b1 = (const float*)d_in[11];
    const float* Wl2 = (const float*)d_in[12], *bl2 = (const float*)d_in[13];
    const float* Wr2 = (const float*)d_in[14], *g2 = (const float*)d_in[15], *b2 = (const float*)d_in[16];

    k_init<<<(NROWS4 + TB - 1) / TB, TB>>>(x, (const long long*)ei);
    k_hist<<<EBLK, TB>>>(ei);
    k_scan1<<<SCAN_NB, 1024>>>();
    k_scan3b<<<NBLK, TB>>>();
    k_scatter<<<EBLK, TB>>>(ei);
    k_wsplit_all<<<384, TB>>>(Wl0, Wr0, Wl1, Wr1, Wl2, Wr2);

    // layer 0
    k_aggregate<<<AGG_BLK, TB>>>(t0);
    k_gemm_mma<<<GEMM_BLK, TB, SM_TOTAL>>>(agg16, t0, whi, wlo, bl0, g0, b0,
                                           nullptr, t1, 0);
    // layer 1
    k_aggregate<<<AGG_BLK, TB>>>(t1);
    k_gemm_mma<<<GEMM_BLK, TB, SM_TOTAL>>>(agg16, t1, whi + 32768, wlo + 32768, bl1, g1, b1,
                                           nullptr, t0, 0);
    // layer 2
    k_aggregate<<<AGG_BLK, TB>>>(t0);
    k_gemm_mma<<<GEMM_BLK, TB, SM_TOTAL>>>(agg16, t0, whi + 65536, wlo + 65536, bl2, g2, b2,
                                           (float*)d_out, nullptr, 1);
}

// round 8
// speedup vs baseline: 2.0650x; 1.1735x over previous
#include <cuda_runtime.h>
#include <cuda_fp16.h>
#include <math.h>
#include <cstdint>

#define NN 100000
#define EE 1600000
#define DD 128
#define NROWS4 ((NN * DD) / 4)

// ---------------- scratch (static device globals; no allocation) -------------
__device__ __align__(16) __half g_t0[NN * DD];     // activation ping (starts as x)
__device__ __align__(16) __half g_t1[NN * DD];     // activation pong
__device__ __align__(16) __half g_agg16[NN * DD];  // mean aggregate

__device__ int   g_col[EE];
__device__ int   g_cnt[NN];          // zero-initialized; re-zeroed by k_scan3b
__device__ int   g_rowptr[NN + 1];
__device__ int   g_wcur[NN];
__device__ float g_invdeg[NN];
__device__ int   g_tmp[NN];
__device__ int   g_bsum[128];
__device__ int   g_is64;

// transposed fp16 weights per layer: [n=128][k=256]
__device__ __align__(16) __half g_wt[3][128 * 256];

// ================= helpers =====================================================
__device__ __forceinline__ uint32_t smem_u32(const void* p) {
    uint32_t a;
    asm("{ .reg .u64 t; cvta.to.shared.u64 t, %1; cvt.u32.u64 %0, t; }" : "=r"(a) : "l"(p));
    return a;
}
__device__ __forceinline__ void ldm_x4(uint32_t* r, uint32_t addr) {
    asm volatile("ldmatrix.sync.aligned.m8n8.x4.shared.b16 {%0,%1,%2,%3}, [%4];"
                 : "=r"(r[0]), "=r"(r[1]), "=r"(r[2]), "=r"(r[3]) : "r"(addr));
}
__device__ __forceinline__ void mma16816(float* c, const uint32_t* a, uint32_t b0, uint32_t b1) {
    asm volatile(
        "mma.sync.aligned.m16n8k16.row.col.f32.f16.f16.f32 "
        "{%0,%1,%2,%3},{%4,%5,%6,%7},{%8,%9},{%0,%1,%2,%3};"
        : "+f"(c[0]), "+f"(c[1]), "+f"(c[2]), "+f"(c[3])
        : "r"(a[0]), "r"(a[1]), "r"(a[2]), "r"(a[3]), "r"(b0), "r"(b1));
}
__device__ __forceinline__ void cp_async16z(uint32_t dst, const void* src, int ok) {
    asm volatile("cp.async.cg.shared.global [%0], [%1], 16, %2;"
                 :: "r"(dst), "l"(src), "r"(ok ? 16 : 0) : "memory");
}
__device__ __forceinline__ uint32_t packh2(float a, float b) {
    __half2 h = __floats2half2_rn(a, b);
    return *(uint32_t*)&h;
}

// ---------------- fused init: x -> fp16 convert + degree histogram -------------
__global__ void k_inithist(const float* __restrict__ x, const void* __restrict__ ei) {
    __shared__ int is64s;
    if (threadIdx.x < 32) {
        const long long* p = (const long long*)ei;
        long long v = p[threadIdx.x];
        int bad = (v < 0 || v >= NN) ? 1 : 0;
        unsigned m = __ballot_sync(0xffffffffu, bad);
        if (threadIdx.x == 0) {
            is64s = (m == 0) ? 1 : 0;
            if (blockIdx.x == 0) g_is64 = is64s;   // for k_scatter later
        }
    }
    __syncthreads();
    int i = blockIdx.x * blockDim.x + threadIdx.x;
    if (i < NROWS4) {
        float4 v = ((const float4*)x)[i];
        ((uint2*)g_t0)[i] = make_uint2(packh2(v.x, v.y), packh2(v.z, v.w));
    }
    if (i < EE) {
        int d = is64s ? (int)((const long long*)ei)[EE + i] : ((const int*)ei)[EE + i];
        atomicAdd(&g_cnt[d], 1);
    }
}

// ---------------- CSR build -----------------------------------------------------
__global__ void k_scan1() {
    __shared__ int s[1024];
    int tid = threadIdx.x;
    int gid = blockIdx.x * 1024 + tid;
    int v = (gid < NN) ? g_cnt[gid] : 0;
    s[tid] = v;
    __syncthreads();
    for (int off = 1; off < 1024; off <<= 1) {
        int t = (tid >= off) ? s[tid - off] : 0;
        __syncthreads();
        s[tid] += t;
        __syncthreads();
    }
    int incl = s[tid];
    if (gid < NN) g_tmp[gid] = incl - v;
    if (tid == 1023) g_bsum[blockIdx.x] = incl;
}
__global__ void k_scan3b() {
    __shared__ int base;
    int sbk = blockIdx.x >> 2;
    if (threadIdx.x < 32) {
        int a = 0;
        for (int i = threadIdx.x; i < sbk; i += 32) a += g_bsum[i];
#pragma unroll
        for (int o = 16; o > 0; o >>= 1) a += __shfl_xor_sync(0xffffffffu, a, o);
        if (threadIdx.x == 0) base = a;
    }
    __syncthreads();
    int i = blockIdx.x * 256 + threadIdx.x;
    if (i < NN) {
        int rp = g_tmp[i] + base;
        g_rowptr[i] = rp;
        g_wcur[i] = rp;
        int c = g_cnt[i];
        g_cnt[i] = 0;                       // self-clean for next graph replay
        g_invdeg[i] = 1.0f / (float)(c > 1 ? c : 1);
        if (i == 0) g_rowptr[NN] = EE;
    }
}
__global__ void k_scatter(const void* __restrict__ ei) {
    int e = blockIdx.x * blockDim.x + threadIdx.x;
    if (e >= EE) return;
    int s, d;
    if (g_is64) {
        const long long* p = (const long long*)ei;
        s = (int)p[e]; d = (int)p[EE + e];
    } else {
        const int* p = (const int*)ei;
        s = p[e]; d = p[EE + e];
    }
    g_col[atomicAdd(&g_wcur[d], 1)] = s;
}

// ---------------- mean aggregation: one warp per node, fp16 in/out -------------
__global__ void k_aggregate(const __half* __restrict__ tb) {
    int warp = (blockIdx.x * blockDim.x + threadIdx.x) >> 5;
    int lane = threadIdx.x & 31;
    if (warp >= NN) return;
    int beg = g_rowptr[warp];
    int end = g_rowptr[warp + 1];
    float a0 = 0.f, a1 = 0.f, a2 = 0.f, a3 = 0.f;
    int j = beg;
    for (; j + 3 < end; j += 4) {
        int s0 = __ldg(&g_col[j]), s1 = __ldg(&g_col[j + 1]);
        int s2 = __ldg(&g_col[j + 2]), s3 = __ldg(&g_col[j + 3]);
        uint2 v0 = *(const uint2*)(tb + (size_t)s0 * DD + lane * 4);
        uint2 v1 = *(const uint2*)(tb + (size_t)s1 * DD + lane * 4);
        uint2 v2 = *(const uint2*)(tb + (size_t)s2 * DD + lane * 4);
        uint2 v3 = *(const uint2*)(tb + (size_t)s3 * DD + lane * 4);
        float2 p;
        p = __half22float2(*(__half2*)&v0.x); a0 += p.x; a1 += p.y;
        p = __half22float2(*(__half2*)&v0.y); a2 += p.x; a3 += p.y;
        p = __half22float2(*(__half2*)&v1.x); a0 += p.x; a1 += p.y;
        p = __half22float2(*(__half2*)&v1.y); a2 += p.x; a3 += p.y;
        p = __half22float2(*(__half2*)&v2.x); a0 += p.x; a1 += p.y;
        p = __half22float2(*(__half2*)&v2.y); a2 += p.x; a3 += p.y;
        p = __half22float2(*(__half2*)&v3.x); a0 += p.x; a1 += p.y;
        p = __half22float2(*(__half2*)&v3.y); a2 += p.x; a3 += p.y;
    }
    for (; j < end; j++) {
        int s0 = __ldg(&g_col[j]);
        uint2 v0 = *(const uint2*)(tb + (size_t)s0 * DD + lane * 4);
        float2 p;
        p = __half22float2(*(__half2*)&v0.x); a0 += p.x; a1 += p.y;
        p = __half22float2(*(__half2*)&v0.y); a2 += p.x; a3 += p.y;
    }
    float id = g_invdeg[warp];
    *(uint2*)(g_agg16 + (size_t)warp * DD + lane * 4) =
        make_uint2(packh2(a0 * id, a1 * id), packh2(a2 * id, a3 * id));
}

// ---------------- weight transpose to fp16 (all 3 layers) ----------------------
__global__ void k_wsplit_all(const float* __restrict__ Wl0, const float* __restrict__ Wr0,
                             const float* __restrict__ Wl1, const float* __restrict__ Wr1,
                             const float* __restrict__ Wl2, const float* __restrict__ Wr2) {
    int idx = blockIdx.x * blockDim.x + threadIdx.x;
    if (idx >= 3 * 128 * 256) return;
    int l = idx >> 15;
    int r = idx & 32767;
    int k = r & 255, n = r >> 8;
    const float* Wl = (l == 0) ? Wl0 : ((l == 1) ? Wl1 : Wl2);
    const float* Wr = (l == 0) ? Wr0 : ((l == 1) ? Wr1 : Wr2);
    float w = (k < 128) ? Wl[k * 128 + n] : Wr[(k - 128) * 128 + n];
    g_wt[l][n * 256 + k] = __float2half_rn(w);
}

// ---------------- HMMA GEMM + bias + LayerNorm + ELU / L2-norm -----------------
// 32KB smem: A fp16 (16KB) + W fp16 (16KB), both 128x64, 128B rows, swizzled
#define AS_T  0
#define WS_T  16384
#define SM_TOTAL 32768

__global__ __launch_bounds__(256, 2)
void k_gemm_mma(const __half* __restrict__ Agg, const __half* __restrict__ X,
                const __half* __restrict__ W,
                const float* __restrict__ bl, const float* __restrict__ gg,
                const float* __restrict__ bb,
                float* __restrict__ outf, __half* __restrict__ outh, int mode)
{
    extern __shared__ char smem[];
    uint32_t sb = smem_u32(smem);
    int tid = threadIdx.x;
    int wid = tid >> 5;
    int lane = tid & 31;
    int row0 = blockIdx.x * 128;
    int m0 = (wid & 3) * 32;
    int n0 = (wid >> 2) * 64;
    int t = lane & 3, g = lane >> 2;

    float acc[2][8][4];
#pragma unroll
    for (int mi = 0; mi < 2; mi++)
#pragma unroll
        for (int ni = 0; ni < 8; ni++)
#pragma unroll
            for (int q = 0; q < 4; q++) acc[mi][ni][q] = 0.f;

    uint32_t swzm = (uint32_t)(lane & 7) << 4;
    uint32_t a_row = m0 + (lane & 7) + ((lane >> 3) & 1) * 8;
    uint32_t a_kb = ((lane >> 4) & 1) * 16;
    uint32_t aoff[2] = { a_row * 128u, (a_row + 16u) * 128u };
    uint32_t jj = lane >> 3;
    uint32_t b_kb = (jj & 1) * 16;
    uint32_t b_row = n0 + (jj >> 1) * 8 + (lane & 7);
    uint32_t boff[4];
#pragma unroll
    for (int p = 0; p < 4; p++) boff[p] = (b_row + p * 16u) * 128u;

    int srow = tid >> 1, half = tid & 1;
    uint32_t sm = (uint32_t)(srow & 7) << 4;
    int grow = row0 + srow;
    int rok = grow < NN;
    int grc = rok ? grow : 0;
    uint32_t rb = (uint32_t)srow * 128u;

    for (int c = 0; c < 4; c++) {
        if (c) __syncthreads();
        {
            const __half* pa = ((c < 2) ? Agg : X) + (size_t)grc * 128 + (c & 1) * 64 + half * 32;
            const __half* pw = W + srow * 256 + c * 64 + half * 32;
#pragma unroll
            for (int q = 0; q < 4; q++) {
                uint32_t off = rb + (((uint32_t)(half * 64 + q * 16)) ^ sm);
                cp_async16z(sb + AS_T + off, pa + q * 8, rok);
                cp_async16z(sb + WS_T + off, pw + q * 8, 1);
            }
            asm volatile("cp.async.commit_group;" ::: "memory");
            asm volatile("cp.async.wait_group 0;" ::: "memory");
        }
        __syncthreads();

#pragma unroll
        for (int ks = 0; ks < 4; ks++) {
            uint32_t kxa = ((uint32_t)(ks * 32) + a_kb) ^ swzm;
            uint32_t kxb = ((uint32_t)(ks * 32) + b_kb) ^ swzm;
            uint32_t ar[2][4], br[4][4];
#pragma unroll
            for (int mi = 0; mi < 2; mi++)
                ldm_x4(ar[mi], sb + AS_T + aoff[mi] + kxa);
#pragma unroll
            for (int p = 0; p < 4; p++)
                ldm_x4(br[p], sb + WS_T + boff[p] + kxb);
#pragma unroll
            for (int mi = 0; mi < 2; mi++) {
#pragma unroll
                for (int p = 0; p < 4; p++) {
                    mma16816(acc[mi][2 * p],     ar[mi], br[p][0], br[p][1]);
                    mma16816(acc[mi][2 * p + 1], ar[mi], br[p][2], br[p][3]);
                }
            }
        }
    }
    __syncthreads();

    // ---- epilogue: bias + LN (+ELU / L2-normalize) ----
    const float2* bl2 = (const float2*)bl;
    const float2* g2 = (const float2*)gg;
    const float2* b2 = (const float2*)bb;
    float2 blv[8], gv[8], bv[8];
#pragma unroll
    for (int ni = 0; ni < 8; ni++) {
        int cp = n0 / 2 + ni * 4 + t;
        blv[ni] = __ldg(&bl2[cp]);
        gv[ni] = __ldg(&g2[cp]);
        bv[ni] = __ldg(&b2[cp]);
    }
    float s1[4] = {0, 0, 0, 0}, s2[4] = {0, 0, 0, 0};
#pragma unroll
    for (int mi = 0; mi < 2; mi++)
#pragma unroll
        for (int ni = 0; ni < 8; ni++) {
            float a0 = acc[mi][ni][0] + blv[ni].x;
            float a1 = acc[mi][ni][1] + blv[ni].y;
            float a2 = acc[mi][ni][2] + blv[ni].x;
            float a3 = acc[mi][ni][3] + blv[ni].y;
            acc[mi][ni][0] = a0; acc[mi][ni][1] = a1;
            acc[mi][ni][2] = a2; acc[mi][ni][3] = a3;
            s1[2 * mi] += a0 + a1;       s2[2 * mi] += a0 * a0 + a1 * a1;
            s1[2 * mi + 1] += a2 + a3;   s2[2 * mi + 1] += a2 * a2 + a3 * a3;
        }
#pragma unroll
    for (int q = 0; q < 4; q++) {
        s1[q] += __shfl_xor_sync(0xffffffffu, s1[q], 1);
        s1[q] += __shfl_xor_sync(0xffffffffu, s1[q], 2);
        s2[q] += __shfl_xor_sync(0xffffffffu, s2[q], 1);
        s2[q] += __shfl_xor_sync(0xffffffffu, s2[q], 2);
    }
    float2* red = (float2*)smem;
    float* red2 = (float*)(smem + 2048);
    int hh = wid >> 2;
    int R[4] = { m0 + g, m0 + 8 + g, m0 + 16 + g, m0 + 24 + g };
    if (t == 0) {
#pragma unroll
        for (int q = 0; q < 4; q++) red[hh * 128 + R[q]] = make_float2(s1[q], s2[q]);
    }
    __syncthreads();
    float mu[4], rs[4];
#pragma unroll
    for (int q = 0; q < 4; q++) {
        float2 o = red[(1 - hh) * 128 + R[q]];
        float t1 = s1[q] + o.x, t2 = s2[q] + o.y;
        float m = t1 * (1.0f / 128.0f);
        float var = t2 * (1.0f / 128.0f) - m * m;
        mu[q] = m;
        rs[q] = rsqrtf(var + 1e-5f);
    }
    float qs[4] = {0, 0, 0, 0};
#pragma unroll
    for (int mi = 0; mi < 2; mi++)
#pragma unroll
        for (int ni = 0; ni < 8; ni++) {
            float y0 = (acc[mi][ni][0] - mu[2 * mi]) * rs[2 * mi] * gv[ni].x + bv[ni].x;
            float y1 = (acc[mi][ni][1] - mu[2 * mi]) * rs[2 * mi] * gv[ni].y + bv[ni].y;
            float y2 = (acc[mi][ni][2] - mu[2 * mi + 1]) * rs[2 * mi + 1] * gv[ni].x + bv[ni].x;
            float y3 = (acc[mi][ni][3] - mu[2 * mi + 1]) * rs[2 * mi + 1] * gv[ni].y + bv[ni].y;
            if (mode == 0) {
                y0 = (y0 > 0.f) ? y0 : expm1f(y0);
                y1 = (y1 > 0.f) ? y1 : expm1f(y1);
                y2 = (y2 > 0.f) ? y2 : expm1f(y2);
                y3 = (y3 > 0.f) ? y3 : expm1f(y3);
            } else {
                qs[2 * mi] += y0 * y0 + y1 * y1;
                qs[2 * mi + 1] += y2 * y2 + y3 * y3;
            }
            acc[mi][ni][0] = y0; acc[mi][ni][1] = y1;
            acc[mi][ni][2] = y2; acc[mi][ni][3] = y3;
        }
    float sc[4] = {1.f, 1.f, 1.f, 1.f};
    if (mode == 1) {
#pragma unroll
        for (int q = 0; q < 4; q++) {
            qs[q] += __shfl_xor_sync(0xffffffffu, qs[q], 1);
            qs[q] += __shfl_xor_sync(0xffffffffu, qs[q], 2);
        }
        if (t == 0) {
#pragma unroll
            for (int q = 0; q < 4; q++) red2[hh * 128 + R[q]] = qs[q];
        }
        __syncthreads();
#pragma unroll
        for (int q = 0; q < 4; q++) {
            float tot = qs[q] + red2[(1 - hh) * 128 + R[q]];
            sc[q] = 1.0f / fmaxf(sqrtf(tot), 1e-12f);
        }
    }
#pragma unroll
    for (int mi = 0; mi < 2; mi++) {
        int rA = row0 + R[2 * mi];
        int rB = row0 + R[2 * mi + 1];
#pragma unroll
        for (int ni = 0; ni < 8; ni++) {
            int col = n0 + ni * 8 + t * 2;
            float y0 = acc[mi][ni][0] * sc[2 * mi];
            float y1 = acc[mi][ni][1] * sc[2 * mi];
            float y2 = acc[mi][ni][2] * sc[2 * mi + 1];
            float y3 = acc[mi][ni][3] * sc[2 * mi + 1];
            if (mode == 0) {
                if (rA < NN)
                    *(uint32_t*)(outh + (size_t)rA * 128 + col) = packh2(y0, y1);
                if (rB < NN)
                    *(uint32_t*)(outh + (size_t)rB * 128 + col) = packh2(y2, y3);
            } else {
                if (rA < NN)
                    *(float2*)(outf + (size_t)rA * 128 + col) = make_float2(y0, y1);
                if (rB < NN)
                    *(float2*)(outf + (size_t)rB * 128 + col) = make_float2(y2, y3);
            }
        }
    }
}

// ---------------- launch --------------------------------------------------------
extern "C" void kernel_launch(void* const* d_in, const int* in_sizes, int n_in,
                              void* d_out, int out_size) {
    const float* x = (const float*)d_in[0];
    const void* ei = d_in[1];

    __half *t0, *t1, *agg16, *wt;
    cudaGetSymbolAddress((void**)&t0, g_t0);
    cudaGetSymbolAddress((void**)&t1, g_t1);
    cudaGetSymbolAddress((void**)&agg16, g_agg16);
    cudaGetSymbolAddress((void**)&wt, g_wt);

    cudaFuncSetAttribute(k_gemm_mma, cudaFuncAttributeMaxDynamicSharedMemorySize, SM_TOTAL);

    const int TB = 256;
    const int EBLK = (EE + TB - 1) / TB;
    const int SCAN_NB = (NN + 1023) / 1024;
    const int NBLK = (NN + TB - 1) / TB;
    const int AGG_BLK = (NN * 32 + TB - 1) / TB;
    const int GEMM_BLK = (NN + 127) / 128;
    const int IH_BLK = (NROWS4 + TB - 1) / TB;   // covers both convert and hist ranges

    const float* Wl0 = (const float*)d_in[2], *bl0 = (const float*)d_in[3];
    const float* Wr0 = (const float*)d_in[4], *g0 = (const float*)d_in[5], *b0 = (const float*)d_in[6];
    const float* Wl1 = (const float*)d_in[7], *bl1 = (const float*)d_in[8];
    const float* Wr1 = (const float*)d_in[9], *g1 = (const float*)d_in[10], *b1 = (const float*)d_in[11];
    const float* Wl2 = (const float*)d_in[12], *bl2 = (const float*)d_in[13];
    const float* Wr2 = (const float*)d_in[14], *g2 = (const float*)d_in[15], *b2 = (const float*)d_in[16];

    k_inithist<<<IH_BLK, TB>>>(x, ei);
    k_scan1<<<SCAN_NB, 1024>>>();
    k_scan3b<<<NBLK, TB>>>();
    k_scatter<<<EBLK, TB>>>(ei);
    k_wsplit_all<<<384, TB>>>(Wl0, Wr0, Wl1, Wr1, Wl2, Wr2);

    // layer 0
    k_aggregate<<<AGG_BLK, TB>>>(t0);
    k_gemm_mma<<<GEMM_BLK, TB, SM_TOTAL>>>(agg16, t0, wt, bl0, g0, b0,
                                           nullptr, t1, 0);
    // layer 1
    k_aggregate<<<AGG_BLK, TB>>>(t1);
    k_gemm_mma<<<GEMM_BLK, TB, SM_TOTAL>>>(agg16, t1, wt + 32768, bl1, g1, b1,
                                           nullptr, t0, 0);
    // layer 2
    k_aggregate<<<AGG_BLK, TB>>>(t0);
    k_gemm_mma<<<GEMM_BLK, TB, SM_TOTAL>>>(agg16, t0, wt + 65536, bl2, g2, b2,
                                           (float*)d_out, nullptr, 1);
}